// round 4
// baseline (speedup 1.0000x reference)
#include <cuda_runtime.h>
#include <cuda_bf16.h>
#include <cstdint>

// Problem constants (shapes fixed by the dataset)
#define NN 100000
#define EE 1600000
#define F0 256
#define FH 128
#define FC 40

// ---------------- static device scratch (no allocation allowed) ----------------
__device__ float g_h[(size_t)NN * FH];     // pre-aggregation features (X @ W)
__device__ float g_a[(size_t)NN * FH];     // post-aggregation features
__device__ int   g_deg[NN];
__device__ int   g_cur[NN];
__device__ float g_dinv[NN];
__device__ int   g_rowptr[NN + 1];
__device__ int   g_col[EE];
__device__ float g_w[EE];                  // dinv[src] per CSR slot
__device__ int   g_is64;                   // edge_index dtype flag (detected on device)

// ---------------- edge dtype detection ----------------
// If edge_index is int64 (values < 100000), every odd 32-bit word is 0.
// If it is int32, odd words are random node indices (virtually never all 0).
__global__ void detect_kernel(const int* __restrict__ ei32, int total_words) {
    __shared__ int acc;
    if (threadIdx.x == 0) acc = 0;
    __syncthreads();
    int v = 0;
    int lim = min(total_words, 8192);
    for (int i = 1 + 2 * threadIdx.x; i < lim; i += 2 * blockDim.x) v |= ei32[i];
    if (v) atomicOr(&acc, 1);
    __syncthreads();
    if (threadIdx.x == 0) g_is64 = (acc == 0) ? 1 : 0;
}

__device__ __forceinline__ int load_edge(const void* ei, long long idx, int is64) {
    if (is64) return (int)((const long long*)ei)[idx];
    return ((const int*)ei)[idx];
}

// ---------------- graph preprocessing ----------------

__global__ void zero_kernel(int n) {
    int i = blockIdx.x * blockDim.x + threadIdx.x;
    if (i < n) { g_deg[i] = 0; g_cur[i] = 0; }
}

__global__ void deg_kernel(const void* __restrict__ ei, int E) {
    int i = blockIdx.x * blockDim.x + threadIdx.x;
    if (i >= E) return;
    int is64 = g_is64;
    int d = load_edge(ei, (long long)E + i, is64);   // dst = second row
    if ((unsigned)d < (unsigned)NN) atomicAdd(&g_deg[d], 1);
}

__global__ void dinv_kernel(int n) {
    int i = blockIdx.x * blockDim.x + threadIdx.x;
    if (i < n) g_dinv[i] = rsqrtf((float)g_deg[i] + 1.0f);
}

// Single-block exclusive scan of g_deg -> g_rowptr
__global__ void scan_kernel(int n) {
    __shared__ int sh[1024];
    int tid = threadIdx.x;
    int chunk = (n + 1023) >> 10;
    int start = tid * chunk;
    int end = min(start + chunk, n);
    int sum = 0;
    for (int i = start; i < end; i++) sum += g_deg[i];
    sh[tid] = sum;
    __syncthreads();
    for (int off = 1; off < 1024; off <<= 1) {
        int v = 0;
        if (tid >= off) v = sh[tid - off];
        __syncthreads();
        sh[tid] += v;
        __syncthreads();
    }
    int run = sh[tid] - sum;  // exclusive prefix
    for (int i = start; i < end; i++) { g_rowptr[i] = run; run += g_deg[i]; }
    if (end == n) g_rowptr[n] = run;
}

__global__ void scatter_kernel(const void* __restrict__ ei, int E) {
    int i = blockIdx.x * blockDim.x + threadIdx.x;
    if (i >= E) return;
    int is64 = g_is64;
    int s = load_edge(ei, i, is64);                  // src = first row
    int d = load_edge(ei, (long long)E + i, is64);   // dst = second row
    if ((unsigned)s >= (unsigned)NN || (unsigned)d >= (unsigned)NN) return;
    int pos = g_rowptr[d] + atomicAdd(&g_cur[d], 1);
    g_col[pos] = s;
    g_w[pos]   = g_dinv[s];
}

// ---------------- SGEMM body: C[M,N] = A[M,K] @ B[K,N] (+ optional bias) ----
// BM=64, BN=64, BK=16, 256 threads, 4x4 microtile per thread.
__device__ __forceinline__ void sgemm_body(
    const float* __restrict__ A, const float* __restrict__ B,
    const float* __restrict__ bias, float* __restrict__ C,
    int M, int N, int K)
{
    const int BM = 64, BN = 64, BK = 16, TM = 4, TN = 4;
    __shared__ float As[BK][BM + 4];
    __shared__ float Bs[BK][BN];

    int tid = threadIdx.x;                 // 256 threads
    int tx = tid % 16, ty = tid / 16;
    int rowBlock = blockIdx.x * BM;
    int colBlock = blockIdx.y * BN;

    float acc[TM][TN] = {};

    int aR = tid >> 2;          // 0..63
    int aC = (tid & 3) * 4;     // 0,4,8,12
    int bR = tid >> 4;          // 0..15
    int bC = (tid & 15) * 4;    // 0..60

    for (int k0 = 0; k0 < K; k0 += BK) {
        int gr = rowBlock + aR;
        float4 av = make_float4(0.f, 0.f, 0.f, 0.f);
        if (gr < M) av = *(const float4*)(A + (size_t)gr * K + k0 + aC);
        As[aC + 0][aR] = av.x; As[aC + 1][aR] = av.y;
        As[aC + 2][aR] = av.z; As[aC + 3][aR] = av.w;

        int gc = colBlock + bC;
        float4 bv;
        if (gc + 3 < N) {
            bv = *(const float4*)(B + (size_t)(k0 + bR) * N + gc);
        } else {
            float t0 = (gc + 0 < N) ? B[(size_t)(k0 + bR) * N + gc + 0] : 0.f;
            float t1 = (gc + 1 < N) ? B[(size_t)(k0 + bR) * N + gc + 1] : 0.f;
            float t2 = (gc + 2 < N) ? B[(size_t)(k0 + bR) * N + gc + 2] : 0.f;
            float t3 = (gc + 3 < N) ? B[(size_t)(k0 + bR) * N + gc + 3] : 0.f;
            bv = make_float4(t0, t1, t2, t3);
        }
        *(float4*)&Bs[bR][bC] = bv;
        __syncthreads();

        #pragma unroll
        for (int k = 0; k < BK; k++) {
            float4 ra = *(const float4*)&As[k][ty * TM];
            float4 rb = *(const float4*)&Bs[k][tx * TN];
            float a0[4] = {ra.x, ra.y, ra.z, ra.w};
            float b0[4] = {rb.x, rb.y, rb.z, rb.w};
            #pragma unroll
            for (int i = 0; i < 4; i++)
                #pragma unroll
                for (int j = 0; j < 4; j++)
                    acc[i][j] += a0[i] * b0[j];
        }
        __syncthreads();
    }

    #pragma unroll
    for (int i = 0; i < TM; i++) {
        int m = rowBlock + ty * TM + i;
        if (m >= M) continue;
        #pragma unroll
        for (int j = 0; j < TN; j++) {
            int nn = colBlock + tx * TN + j;
            if (nn >= N) continue;
            float v = acc[i][j];
            if (bias) v += bias[nn];
            C[(size_t)m * N + nn] = v;
        }
    }
}

// Thin wrappers binding device-global scratch (no host symbol API needed).
__global__ void sgemm_x_w1(const float* __restrict__ A, const float* __restrict__ B,
                           int M, int N, int K) {
    sgemm_body(A, B, nullptr, g_h, M, N, K);
}
__global__ void sgemm_a_w2(const float* __restrict__ B, int M, int N, int K) {
    sgemm_body(g_a, B, nullptr, g_h, M, N, K);
}
__global__ void sgemm_a_wc(const float* __restrict__ B, const float* __restrict__ bias,
                           float* __restrict__ C, int M, int N, int K) {
    sgemm_body(g_a, B, bias, C, M, N, K);
}

// ---------------- aggregation: warp per node, 128 features as 32 x float4 ----
// g_a[i] = relu( dinv[i] * sum_e w_e*g_h[src_e] + dinv[i]^2 * g_h[i] + bias )
__global__ void agg_kernel(const float* __restrict__ bias, int n) {
    int warp = (blockIdx.x * blockDim.x + threadIdx.x) >> 5;
    if (warp >= n) return;
    int lane = threadIdx.x & 31;

    int beg = g_rowptr[warp];
    int end = g_rowptr[warp + 1];

    const float4* hv = (const float4*)g_h;
    float4 acc = make_float4(0.f, 0.f, 0.f, 0.f);

    for (int e = beg; e < end; ++e) {
        int s = g_col[e];
        float w = g_w[e];
        float4 v = hv[(size_t)s * 32 + lane];
        acc.x += w * v.x; acc.y += w * v.y;
        acc.z += w * v.z; acc.w += w * v.w;
    }

    float di  = g_dinv[warp];
    float di2 = di * di;
    float4 hs = hv[(size_t)warp * 32 + lane];
    float4 bb = ((const float4*)bias)[lane];

    float4 r;
    r.x = fmaxf(di * acc.x + di2 * hs.x + bb.x, 0.f);
    r.y = fmaxf(di * acc.y + di2 * hs.y + bb.y, 0.f);
    r.z = fmaxf(di * acc.z + di2 * hs.z + bb.z, 0.f);
    r.w = fmaxf(di * acc.w + di2 * hs.w + bb.w, 0.f);

    ((float4*)g_a)[(size_t)warp * 32 + lane] = r;
}

// ---------------- launch ----------------

extern "C" void kernel_launch(void* const* d_in, const int* in_sizes, int n_in,
                              void* d_out, int out_size) {
    const float* x   = (const float*)d_in[0];
    const void*  ei  = d_in[1];                 // int32 or int64 — detected on device
    const float* W1  = (const float*)d_in[2];
    const float* b1  = (const float*)d_in[3];
    const float* W2  = (const float*)d_in[4];
    const float* b2  = (const float*)d_in[5];
    const float* Wc  = (const float*)d_in[6];
    const float* bc  = (const float*)d_in[7];
    float*       out = (float*)d_out;

    const int n = in_sizes[0] / F0;   // 100000
    const int E = in_sizes[1] / 2;    // 1600000 (element count is dtype-agnostic)

    // ---- dtype detection + graph preprocessing (plain kernels; capture-safe) ----
    detect_kernel<<<1, 256>>>((const int*)ei, 2 * E);   // conservative word count
    zero_kernel<<<(n + 255) / 256, 256>>>(n);
    int tbE = 256, gbE = (E + tbE - 1) / tbE;
    deg_kernel<<<gbE, tbE>>>(ei, E);
    dinv_kernel<<<(n + 255) / 256, 256>>>(n);
    scan_kernel<<<1, 1024>>>(n);
    scatter_kernel<<<gbE, tbE>>>(ei, E);

    // ---- layer 1: g_h = x @ W1 ; g_a = relu(agg(g_h) + b1) ----
    {
        dim3 grid((n + 63) / 64, (FH + 63) / 64);
        sgemm_x_w1<<<grid, 256>>>(x, W1, n, FH, F0);
        agg_kernel<<<(n + 7) / 8, 256>>>(b1, n);
    }
    // ---- layer 2: g_h = g_a @ W2 ; g_a = relu(agg(g_h) + b2) ----
    {
        dim3 grid((n + 63) / 64, (FH + 63) / 64);
        sgemm_a_w2<<<grid, 256>>>(W2, n, FH, FH);
        agg_kernel<<<(n + 7) / 8, 256>>>(b2, n);
    }
    // ---- classifier: out = g_a @ Wc + bc ----
    {
        dim3 grid((n + 63) / 64, (FC + 63) / 64);
        sgemm_a_wc<<<grid, 256>>>(Wc, bc, out, n, FC, FH);
    }
}

// round 6
// speedup vs baseline: 1.1507x; 1.1507x over previous
#include <cuda_runtime.h>
#include <cuda_bf16.h>
#include <cstdint>

#define NN 100000
#define EE 1600000
#define F0 256
#define FH 128
#define FC 40

// ---------------- static device scratch ----------------
__device__ float g_h[(size_t)NN * FH];
__device__ float g_a[(size_t)NN * FH];
__device__ int   g_deg[NN];
__device__ int   g_cur[NN];
__device__ float g_dinv[NN];
__device__ int   g_rowptr[NN + 1];
__device__ int   g_col[EE];
__device__ float g_w[EE];
__device__ int   g_is64;
// bf16 split-precision operand buffers
__device__ __nv_bfloat16 g_Ahi[(size_t)NN * F0];
__device__ __nv_bfloat16 g_Alo[(size_t)NN * F0];
__device__ __nv_bfloat16 g_W1thi[FH * F0], g_W1tlo[FH * F0];   // [N=128][K=256] K-major
__device__ __nv_bfloat16 g_W2thi[FH * FH], g_W2tlo[FH * FH];   // [N=128][K=128] K-major

// ---------------- helpers ----------------
__device__ __forceinline__ uint32_t smem_u32(const void* p) {
    uint32_t a;
    asm("{ .reg .u64 t; cvta.to.shared.u64 t, %1; cvt.u32.u64 %0, t; }" : "=r"(a) : "l"(p));
    return a;
}
#define LDSM_X4(r0, r1, r2, r3, addr) \
    asm volatile("ldmatrix.sync.aligned.m8n8.x4.shared.b16 {%0,%1,%2,%3}, [%4];" \
                 : "=r"(r0), "=r"(r1), "=r"(r2), "=r"(r3) : "r"(addr))
#define MMA16816(d, a, b) \
    asm volatile("mma.sync.aligned.m16n8k16.row.col.f32.bf16.bf16.f32 " \
                 "{%0,%1,%2,%3}, {%4,%5,%6,%7}, {%8,%9}, {%0,%1,%2,%3};" \
                 : "+f"((d)[0]), "+f"((d)[1]), "+f"((d)[2]), "+f"((d)[3]) \
                 : "r"((a)[0]), "r"((a)[1]), "r"((a)[2]), "r"((a)[3]), \
                   "r"((b)[0]), "r"((b)[1]))

// ---------------- edge dtype detection ----------------
__global__ void detect_kernel(const int* __restrict__ ei32, int total_words) {
    __shared__ int acc;
    if (threadIdx.x == 0) acc = 0;
    __syncthreads();
    int v = 0;
    int lim = min(total_words, 8192);
    for (int i = 1 + 2 * threadIdx.x; i < lim; i += 2 * blockDim.x) v |= ei32[i];
    if (v) atomicOr(&acc, 1);
    __syncthreads();
    if (threadIdx.x == 0) g_is64 = (acc == 0) ? 1 : 0;
}
__device__ __forceinline__ int load_edge(const void* ei, long long idx, int is64) {
    if (is64) return (int)((const long long*)ei)[idx];
    return ((const int*)ei)[idx];
}

// ---------------- graph preprocessing ----------------
__global__ void zero_kernel(int n) {
    int i = blockIdx.x * blockDim.x + threadIdx.x;
    if (i < n) { g_deg[i] = 0; g_cur[i] = 0; }
}
__global__ void deg_kernel(const void* __restrict__ ei, int E) {
    int i = blockIdx.x * blockDim.x + threadIdx.x;
    if (i >= E) return;
    int d = load_edge(ei, (long long)E + i, g_is64);
    if ((unsigned)d < (unsigned)NN) atomicAdd(&g_deg[d], 1);
}
__global__ void dinv_kernel(int n) {
    int i = blockIdx.x * blockDim.x + threadIdx.x;
    if (i < n) g_dinv[i] = rsqrtf((float)g_deg[i] + 1.0f);
}
__global__ void scan_kernel(int n) {
    __shared__ int sh[1024];
    int tid = threadIdx.x;
    int chunk = (n + 1023) >> 10;
    int start = tid * chunk, end = min(start + chunk, n);
    int sum = 0;
    for (int i = start; i < end; i++) sum += g_deg[i];
    sh[tid] = sum;
    __syncthreads();
    for (int off = 1; off < 1024; off <<= 1) {
        int v = 0;
        if (tid >= off) v = sh[tid - off];
        __syncthreads();
        sh[tid] += v;
        __syncthreads();
    }
    int run = sh[tid] - sum;
    for (int i = start; i < end; i++) { g_rowptr[i] = run; run += g_deg[i]; }
    if (end == n) g_rowptr[n] = run;
}
__global__ void scatter_kernel(const void* __restrict__ ei, int E) {
    int i = blockIdx.x * blockDim.x + threadIdx.x;
    if (i >= E) return;
    int is64 = g_is64;
    int s = load_edge(ei, i, is64);
    int d = load_edge(ei, (long long)E + i, is64);
    if ((unsigned)s >= (unsigned)NN || (unsigned)d >= (unsigned)NN) return;
    int pos = g_rowptr[d] + atomicAdd(&g_cur[d], 1);
    g_col[pos] = s;
    g_w[pos]   = g_dinv[s];
}

// ---------------- bf16 hi/lo split conversions ----------------
__global__ void split_src(const float* __restrict__ src, int count) {
    int i = blockIdx.x * blockDim.x + threadIdx.x;
    if (i >= count) return;
    float f = src[i];
    __nv_bfloat16 hi = __float2bfloat16(f);
    g_Ahi[i] = hi;
    g_Alo[i] = __float2bfloat16(f - __bfloat162float(hi));
}
__global__ void split_ga(int count) {
    int i = blockIdx.x * blockDim.x + threadIdx.x;
    if (i >= count) return;
    float f = g_a[i];
    __nv_bfloat16 hi = __float2bfloat16(f);
    g_Ahi[i] = hi;
    g_Alo[i] = __float2bfloat16(f - __bfloat162float(hi));
}
// W[K,N] fp32 -> Wt[N,K] bf16 hi/lo
__global__ void split_wt(const float* __restrict__ W, int K, int which) {
    int i = blockIdx.x * blockDim.x + threadIdx.x;
    if (i >= K * FH) return;
    int k = i / FH, nidx = i % FH;
    float f = W[i];
    __nv_bfloat16 hi = __float2bfloat16(f);
    __nv_bfloat16 lo = __float2bfloat16(f - __bfloat162float(hi));
    if (which == 1) { g_W1thi[nidx * K + k] = hi; g_W1tlo[nidx * K + k] = lo; }
    else           { g_W2thi[nidx * K + k] = hi; g_W2tlo[nidx * K + k] = lo; }
}

// ---------------- mma.sync bf16 GEMM: g_h[M,128] = A[M,K] @ Wt[128,K]^T -------
// BM=128 BN=128 BK=32, 8 warps (4 in M x 2 in N), warp tile 32x64.
// 3-term split precision: AhiBhi + AloBhi + AhiBlo.
#define SKEW 40   // smem row stride in bf16 elems (80B: conflict-free ldmatrix)

__global__ void __launch_bounds__(256, 2) mma_gemm(int layer, int M, int K) {
    __shared__ __nv_bfloat16 sAhi[128 * SKEW];
    __shared__ __nv_bfloat16 sAlo[128 * SKEW];
    __shared__ __nv_bfloat16 sBhi[128 * SKEW];
    __shared__ __nv_bfloat16 sBlo[128 * SKEW];

    const __nv_bfloat16* Bh = (layer == 1) ? g_W1thi : g_W2thi;
    const __nv_bfloat16* Bl = (layer == 1) ? g_W1tlo : g_W2tlo;

    int tid = threadIdx.x, wid = tid >> 5, lane = tid & 31;
    int m0 = blockIdx.x * 128;
    int warp_m = wid & 3, warp_n = wid >> 2;

    float acc[2][8][4] = {};
    uint32_t aAhi = smem_u32(sAhi), aAlo = smem_u32(sAlo);
    uint32_t aBhi = smem_u32(sBhi), aBlo = smem_u32(sBlo);

    int nch = K >> 5;
    for (int c = 0; c < nch; c++) {
        int kc = c << 5;
        // ---- load chunk into smem (each row = 32 bf16 = 4 uint4 segs) ----
        #pragma unroll
        for (int id = tid; id < 512; id += 256) {
            int row = id >> 2, seg = id & 3;
            int gr = m0 + row;
            uint4 vh = make_uint4(0, 0, 0, 0), vl = vh;
            if (gr < M) {
                vh = *(const uint4*)(g_Ahi + (size_t)gr * K + kc + seg * 8);
                vl = *(const uint4*)(g_Alo + (size_t)gr * K + kc + seg * 8);
            }
            *(uint4*)(sAhi + row * SKEW + seg * 8) = vh;
            *(uint4*)(sAlo + row * SKEW + seg * 8) = vl;
            uint4 wh = *(const uint4*)(Bh + (size_t)row * K + kc + seg * 8);
            uint4 wl = *(const uint4*)(Bl + (size_t)row * K + kc + seg * 8);
            *(uint4*)(sBhi + row * SKEW + seg * 8) = wh;
            *(uint4*)(sBlo + row * SKEW + seg * 8) = wl;
        }
        __syncthreads();

        #pragma unroll
        for (int kk = 0; kk < 32; kk += 16) {
            // A fragments (hi & lo), 2 m-tiles of 16
            uint32_t ah[2][4], al[2][4];
            #pragma unroll
            for (int mi = 0; mi < 2; mi++) {
                int row = warp_m * 32 + mi * 16 + (lane & 15);
                int col = kk + (lane >> 4) * 8;
                uint32_t off = (uint32_t)(row * SKEW + col) * 2;
                LDSM_X4(ah[mi][0], ah[mi][1], ah[mi][2], ah[mi][3], aAhi + off);
                LDSM_X4(al[mi][0], al[mi][1], al[mi][2], al[mi][3], aAlo + off);
            }
            // B hi fragments: 8 n-tiles of 8 (loaded in pairs via x4)
            uint32_t b[8][2];
            int g = lane >> 3;
            #pragma unroll
            for (int p = 0; p < 4; p++) {
                int nrow = warp_n * 64 + p * 16 + (g >> 1) * 8 + (lane & 7);
                int col = kk + (g & 1) * 8;
                uint32_t off = (uint32_t)(nrow * SKEW + col) * 2;
                uint32_t r0, r1, r2, r3;
                LDSM_X4(r0, r1, r2, r3, aBhi + off);
                b[p * 2][0] = r0; b[p * 2][1] = r1;
                b[p * 2 + 1][0] = r2; b[p * 2 + 1][1] = r3;
            }
            // terms 1+2: Ahi*Bhi + Alo*Bhi
            #pragma unroll
            for (int mi = 0; mi < 2; mi++)
                #pragma unroll
                for (int ni = 0; ni < 8; ni++) {
                    MMA16816(acc[mi][ni], ah[mi], b[ni]);
                    MMA16816(acc[mi][ni], al[mi], b[ni]);
                }
            // B lo fragments (reuse registers)
            #pragma unroll
            for (int p = 0; p < 4; p++) {
                int nrow = warp_n * 64 + p * 16 + (g >> 1) * 8 + (lane & 7);
                int col = kk + (g & 1) * 8;
                uint32_t off = (uint32_t)(nrow * SKEW + col) * 2;
                uint32_t r0, r1, r2, r3;
                LDSM_X4(r0, r1, r2, r3, aBlo + off);
                b[p * 2][0] = r0; b[p * 2][1] = r1;
                b[p * 2 + 1][0] = r2; b[p * 2 + 1][1] = r3;
            }
            // term 3: Ahi*Blo
            #pragma unroll
            for (int mi = 0; mi < 2; mi++)
                #pragma unroll
                for (int ni = 0; ni < 8; ni++)
                    MMA16816(acc[mi][ni], ah[mi], b[ni]);
        }
        __syncthreads();
    }

    // ---- epilogue: fragment layout c0,c1=row gid cols 2t,2t+1; c2,c3=row gid+8
    int gid = lane >> 2, tig = lane & 3;
    #pragma unroll
    for (int mi = 0; mi < 2; mi++) {
        #pragma unroll
        for (int ni = 0; ni < 8; ni++) {
            int col = warp_n * 64 + ni * 8 + tig * 2;
            int r0 = m0 + warp_m * 32 + mi * 16 + gid;
            if (r0 < M)
                *(float2*)(g_h + (size_t)r0 * 128 + col) =
                    make_float2(acc[mi][ni][0], acc[mi][ni][1]);
            int r1 = r0 + 8;
            if (r1 < M)
                *(float2*)(g_h + (size_t)r1 * 128 + col) =
                    make_float2(acc[mi][ni][2], acc[mi][ni][3]);
        }
    }
}

// ---------------- SIMT SGEMM (classifier only, N=40) ----------------
__device__ __forceinline__ void sgemm_body(
    const float* __restrict__ A, const float* __restrict__ B,
    const float* __restrict__ bias, float* __restrict__ C, int M, int N, int K) {
    const int BM = 64, BN = 64, BK = 16, TM = 4, TN = 4;
    __shared__ float As[BK][BM + 4];
    __shared__ float Bs[BK][BN];
    int tid = threadIdx.x;
    int tx = tid % 16, ty = tid / 16;
    int rowBlock = blockIdx.x * BM, colBlock = blockIdx.y * BN;
    float acc[TM][TN] = {};
    int aR = tid >> 2, aC = (tid & 3) * 4;
    int bR = tid >> 4, bC = (tid & 15) * 4;
    for (int k0 = 0; k0 < K; k0 += BK) {
        int gr = rowBlock + aR;
        float4 av = make_float4(0.f, 0.f, 0.f, 0.f);
        if (gr < M) av = *(const float4*)(A + (size_t)gr * K + k0 + aC);
        As[aC + 0][aR] = av.x; As[aC + 1][aR] = av.y;
        As[aC + 2][aR] = av.z; As[aC + 3][aR] = av.w;
        int gc = colBlock + bC;
        float4 bv;
        if (gc + 3 < N) {
            bv = *(const float4*)(B + (size_t)(k0 + bR) * N + gc);
        } else {
            float t0 = (gc + 0 < N) ? B[(size_t)(k0 + bR) * N + gc + 0] : 0.f;
            float t1 = (gc + 1 < N) ? B[(size_t)(k0 + bR) * N + gc + 1] : 0.f;
            float t2 = (gc + 2 < N) ? B[(size_t)(k0 + bR) * N + gc + 2] : 0.f;
            float t3 = (gc + 3 < N) ? B[(size_t)(k0 + bR) * N + gc + 3] : 0.f;
            bv = make_float4(t0, t1, t2, t3);
        }
        *(float4*)&Bs[bR][bC] = bv;
        __syncthreads();
        #pragma unroll
        for (int k = 0; k < BK; k++) {
            float4 ra = *(const float4*)&As[k][ty * TM];
            float4 rb = *(const float4*)&Bs[k][tx * TN];
            float a0[4] = {ra.x, ra.y, ra.z, ra.w};
            float b0[4] = {rb.x, rb.y, rb.z, rb.w};
            #pragma unroll
            for (int i = 0; i < 4; i++)
                #pragma unroll
                for (int j = 0; j < 4; j++)
                    acc[i][j] += a0[i] * b0[j];
        }
        __syncthreads();
    }
    #pragma unroll
    for (int i = 0; i < TM; i++) {
        int m = rowBlock + ty * TM + i;
        if (m >= M) continue;
        #pragma unroll
        for (int j = 0; j < TN; j++) {
            int nn = colBlock + tx * TN + j;
            if (nn >= N) continue;
            float v = acc[i][j];
            if (bias) v += bias[nn];
            C[(size_t)m * N + nn] = v;
        }
    }
}
__global__ void sgemm_a_wc(const float* __restrict__ B, const float* __restrict__ bias,
                           float* __restrict__ C, int M, int N, int K) {
    sgemm_body(g_a, B, bias, C, M, N, K);
}

// ---------------- aggregation: warp per node ----------------
__global__ void agg_kernel(const float* __restrict__ bias, int n) {
    int warp = (blockIdx.x * blockDim.x + threadIdx.x) >> 5;
    if (warp >= n) return;
    int lane = threadIdx.x & 31;
    int beg = g_rowptr[warp], end = g_rowptr[warp + 1];
    const float4* hv = (const float4*)g_h;
    float4 acc = make_float4(0.f, 0.f, 0.f, 0.f);
    for (int e = beg; e < end; ++e) {
        int s = g_col[e];
        float w = g_w[e];
        float4 v = hv[(size_t)s * 32 + lane];
        acc.x += w * v.x; acc.y += w * v.y;
        acc.z += w * v.z; acc.w += w * v.w;
    }
    float di = g_dinv[warp], di2 = di * di;
    float4 hs = hv[(size_t)warp * 32 + lane];
    float4 bb = ((const float4*)bias)[lane];
    float4 r;
    r.x = fmaxf(di * acc.x + di2 * hs.x + bb.x, 0.f);
    r.y = fmaxf(di * acc.y + di2 * hs.y + bb.y, 0.f);
    r.z = fmaxf(di * acc.z + di2 * hs.z + bb.z, 0.f);
    r.w = fmaxf(di * acc.w + di2 * hs.w + bb.w, 0.f);
    ((float4*)g_a)[(size_t)warp * 32 + lane] = r;
}

// ---------------- launch ----------------
extern "C" void kernel_launch(void* const* d_in, const int* in_sizes, int n_in,
                              void* d_out, int out_size) {
    const float* x  = (const float*)d_in[0];
    const void*  ei = d_in[1];
    const float* W1 = (const float*)d_in[2];
    const float* b1 = (const float*)d_in[3];
    const float* W2 = (const float*)d_in[4];
    const float* b2 = (const float*)d_in[5];
    const float* Wc = (const float*)d_in[6];
    const float* bc = (const float*)d_in[7];
    float*       out = (float*)d_out;

    const int n = in_sizes[0] / F0;   // 100000
    const int E = in_sizes[1] / 2;    // 1600000

    // ---- dtype detect + graph preprocessing ----
    detect_kernel<<<1, 256>>>((const int*)ei, 2 * E);
    zero_kernel<<<(n + 255) / 256, 256>>>(n);
    int gbE = (E + 255) / 256;
    deg_kernel<<<gbE, 256>>>(ei, E);
    dinv_kernel<<<(n + 255) / 256, 256>>>(n);
    scan_kernel<<<1, 1024>>>(n);
    scatter_kernel<<<gbE, 256>>>(ei, E);

    // ---- weight prep ----
    split_wt<<<(F0 * FH + 255) / 256, 256>>>(W1, F0, 1);
    split_wt<<<(FH * FH + 255) / 256, 256>>>(W2, FH, 2);

    int mBlocks = (n + 127) / 128;

    // ---- layer 1 ----
    split_src<<<(n * F0 + 255) / 256, 256>>>(x, n * F0);
    mma_gemm<<<mBlocks, 256>>>(1, n, F0);
    agg_kernel<<<(n + 7) / 8, 256>>>(b1, n);

    // ---- layer 2 ----
    split_ga<<<(n * FH + 255) / 256, 256>>>(n * FH);
    mma_gemm<<<mBlocks, 256>>>(2, n, FH);
    agg_kernel<<<(n + 7) / 8, 256>>>(b2, n);

    // ---- classifier (fp32 SIMT) ----
    dim3 gridc((n + 63) / 64, (FC + 63) / 64);
    sgemm_a_wc<<<gridc, 256>>>(Wc, bc, out, n, FC, FH);
}

// round 7
// speedup vs baseline: 1.1819x; 1.0271x over previous
#include <cuda_runtime.h>
#include <cuda_bf16.h>
#include <cstdint>

#define NN 100000
#define EE 1600000
#define F0 256
#define FH 128
#define FC 40

// ---------------- static device scratch ----------------
__device__ float g_h[(size_t)NN * FH];
__device__ float g_a[(size_t)NN * FH];
__device__ int   g_deg[NN];
__device__ int   g_cur[NN];
__device__ float g_dinv[NN];
__device__ int   g_rowptr[NN + 1];
__device__ int   g_col[EE];
__device__ float g_w[EE];                 // dinv[src]*dinv[dst] per CSR slot
__device__ int   g_is64;
// bf16 split-precision operand buffers
__device__ __nv_bfloat16 g_Ahi[(size_t)NN * F0];
__device__ __nv_bfloat16 g_Alo[(size_t)NN * F0];
__device__ __nv_bfloat16 g_W1thi[FH * F0], g_W1tlo[FH * F0];   // [N=128][K=256] K-major
__device__ __nv_bfloat16 g_W2thi[FH * FH], g_W2tlo[FH * FH];   // [N=128][K=128] K-major

// ---------------- helpers ----------------
__device__ __forceinline__ uint32_t smem_u32(const void* p) {
    uint32_t a;
    asm("{ .reg .u64 t; cvta.to.shared.u64 t, %1; cvt.u32.u64 %0, t; }" : "=r"(a) : "l"(p));
    return a;
}
#define LDSM_X4(r0, r1, r2, r3, addr) \
    asm volatile("ldmatrix.sync.aligned.m8n8.x4.shared.b16 {%0,%1,%2,%3}, [%4];" \
                 : "=r"(r0), "=r"(r1), "=r"(r2), "=r"(r3) : "r"(addr))
#define MMA16816(d, a, b) \
    asm volatile("mma.sync.aligned.m16n8k16.row.col.f32.bf16.bf16.f32 " \
                 "{%0,%1,%2,%3}, {%4,%5,%6,%7}, {%8,%9}, {%0,%1,%2,%3};" \
                 : "+f"((d)[0]), "+f"((d)[1]), "+f"((d)[2]), "+f"((d)[3]) \
                 : "r"((a)[0]), "r"((a)[1]), "r"((a)[2]), "r"((a)[3]), \
                   "r"((b)[0]), "r"((b)[1]))
#define CP_ASYNC16(dst, src, sz) \
    asm volatile("cp.async.cg.shared.global [%0], [%1], 16, %2;" \
                 :: "r"(dst), "l"(src), "r"(sz) : "memory")
#define CP_COMMIT asm volatile("cp.async.commit_group;" ::: "memory")
#define CP_WAIT(n) asm volatile("cp.async.wait_group %0;" :: "n"(n) : "memory")

// ---------------- edge dtype detection ----------------
__global__ void detect_kernel(const int* __restrict__ ei32, int total_words) {
    __shared__ int acc;
    if (threadIdx.x == 0) acc = 0;
    __syncthreads();
    int v = 0;
    int lim = min(total_words, 8192);
    for (int i = 1 + 2 * threadIdx.x; i < lim; i += 2 * blockDim.x) v |= ei32[i];
    if (v) atomicOr(&acc, 1);
    __syncthreads();
    if (threadIdx.x == 0) g_is64 = (acc == 0) ? 1 : 0;
}
__device__ __forceinline__ int load_edge(const void* ei, long long idx, int is64) {
    if (is64) return (int)((const long long*)ei)[idx];
    return ((const int*)ei)[idx];
}

// ---------------- graph preprocessing ----------------
__global__ void zero_kernel(int n) {
    int i = blockIdx.x * blockDim.x + threadIdx.x;
    if (i < n) { g_deg[i] = 0; g_cur[i] = 0; }
}
__global__ void deg_kernel(const void* __restrict__ ei, int E) {
    int i = blockIdx.x * blockDim.x + threadIdx.x;
    if (i >= E) return;
    int d = load_edge(ei, (long long)E + i, g_is64);
    if ((unsigned)d < (unsigned)NN) atomicAdd(&g_deg[d], 1);
}
__global__ void dinv_kernel(int n) {
    int i = blockIdx.x * blockDim.x + threadIdx.x;
    if (i < n) g_dinv[i] = rsqrtf((float)g_deg[i] + 1.0f);
}
__global__ void scan_kernel(int n) {
    __shared__ int sh[1024];
    int tid = threadIdx.x;
    int chunk = (n + 1023) >> 10;
    int start = tid * chunk, end = min(start + chunk, n);
    int sum = 0;
    for (int i = start; i < end; i++) sum += g_deg[i];
    sh[tid] = sum;
    __syncthreads();
    for (int off = 1; off < 1024; off <<= 1) {
        int v = 0;
        if (tid >= off) v = sh[tid - off];
        __syncthreads();
        sh[tid] += v;
        __syncthreads();
    }
    int run = sh[tid] - sum;
    for (int i = start; i < end; i++) { g_rowptr[i] = run; run += g_deg[i]; }
    if (end == n) g_rowptr[n] = run;
}
__global__ void scatter_kernel(const void* __restrict__ ei, int E) {
    int i = blockIdx.x * blockDim.x + threadIdx.x;
    if (i >= E) return;
    int is64 = g_is64;
    int s = load_edge(ei, i, is64);
    int d = load_edge(ei, (long long)E + i, is64);
    if ((unsigned)s >= (unsigned)NN || (unsigned)d >= (unsigned)NN) return;
    int pos = g_rowptr[d] + atomicAdd(&g_cur[d], 1);
    g_col[pos] = s;
    g_w[pos]   = g_dinv[s] * g_dinv[d];   // full symmetric norm folded in
}

// ---------------- bf16 hi/lo split conversions ----------------
__global__ void split_src(const float* __restrict__ src, int count) {
    int i = blockIdx.x * blockDim.x + threadIdx.x;
    if (i >= count) return;
    float f = src[i];
    __nv_bfloat16 hi = __float2bfloat16(f);
    g_Ahi[i] = hi;
    g_Alo[i] = __float2bfloat16(f - __bfloat162float(hi));
}
// W[K,N] fp32 -> Wt[N,K] bf16 hi/lo
__global__ void split_wt(const float* __restrict__ W, int K, int which) {
    int i = blockIdx.x * blockDim.x + threadIdx.x;
    if (i >= K * FH) return;
    int k = i / FH, nidx = i % FH;
    float f = W[i];
    __nv_bfloat16 hi = __float2bfloat16(f);
    __nv_bfloat16 lo = __float2bfloat16(f - __bfloat162float(hi));
    if (which == 1) { g_W1thi[nidx * K + k] = hi; g_W1tlo[nidx * K + k] = lo; }
    else           { g_W2thi[nidx * K + k] = hi; g_W2tlo[nidx * K + k] = lo; }
}

// ---------------- mma.sync bf16 GEMM, cp.async double-buffered ---------------
// BM=128 BN=128 BK=32, 8 warps (4 in M x 2 in N), warp tile 32x64.
// 3-term split precision: AhiBhi + AloBhi + AhiBlo.
#define SKEW 40                     // smem row stride in bf16 (80B rows)
#define TILE_B (128 * SKEW * 2)     // 10240 bytes per tile
#define STAGE_B (4 * TILE_B)        // Ahi,Alo,Bhi,Blo
#define GSM_TOTAL (2 * STAGE_B)     // 81920 bytes

__device__ __forceinline__ void gemm_load_stage(
    uint32_t sbase, const __nv_bfloat16* __restrict__ Ah, const __nv_bfloat16* __restrict__ Al,
    const __nv_bfloat16* __restrict__ Bh, const __nv_bfloat16* __restrict__ Bl,
    int m0, int kc, int K, int M)
{
    int tid = threadIdx.x;
    #pragma unroll
    for (int it = 0; it < 2; it++) {
        int id = it * 256 + tid;          // 512 ids: 128 rows x 4 segs
        int row = id >> 2, seg = id & 3;
        uint32_t soff = (uint32_t)(row * SKEW + seg * 8) * 2;
        int gr = m0 + row;
        int ok = (gr < M) ? 16 : 0;
        size_t grc = (gr < M) ? (size_t)gr : 0;
        CP_ASYNC16(sbase + soff,               Ah + grc * K + kc + seg * 8, ok);
        CP_ASYNC16(sbase + TILE_B + soff,      Al + grc * K + kc + seg * 8, ok);
        CP_ASYNC16(sbase + 2 * TILE_B + soff,  Bh + (size_t)row * K + kc + seg * 8, 16);
        CP_ASYNC16(sbase + 3 * TILE_B + soff,  Bl + (size_t)row * K + kc + seg * 8, 16);
    }
}

__global__ void __launch_bounds__(256, 2) mma_gemm(int layer, int M, int K) {
    extern __shared__ char smem[];
    uint32_t sb = smem_u32(smem);

    const __nv_bfloat16* Bh = (layer == 1) ? g_W1thi : g_W2thi;
    const __nv_bfloat16* Bl = (layer == 1) ? g_W1tlo : g_W2tlo;

    int tid = threadIdx.x, wid = tid >> 5, lane = tid & 31;
    int m0 = blockIdx.x * 128;
    int warp_m = wid & 3, warp_n = wid >> 2;

    float acc[2][8][4] = {};

    int nch = K >> 5;
    gemm_load_stage(sb, g_Ahi, g_Alo, Bh, Bl, m0, 0, K, M);
    CP_COMMIT;

    for (int c = 0; c < nch; c++) {
        if (c + 1 < nch) {
            gemm_load_stage(sb + ((c + 1) & 1) * STAGE_B, g_Ahi, g_Alo, Bh, Bl,
                            m0, (c + 1) << 5, K, M);
            CP_COMMIT;
            CP_WAIT(1);
        } else {
            CP_WAIT(0);
        }
        __syncthreads();

        uint32_t stg = sb + (c & 1) * STAGE_B;
        uint32_t aAhi = stg, aAlo = stg + TILE_B;
        uint32_t aBhi = stg + 2 * TILE_B, aBlo = stg + 3 * TILE_B;

        #pragma unroll
        for (int kk = 0; kk < 32; kk += 16) {
            uint32_t ah[2][4], al[2][4];
            #pragma unroll
            for (int mi = 0; mi < 2; mi++) {
                int row = warp_m * 32 + mi * 16 + (lane & 15);
                int col = kk + (lane >> 4) * 8;
                uint32_t off = (uint32_t)(row * SKEW + col) * 2;
                LDSM_X4(ah[mi][0], ah[mi][1], ah[mi][2], ah[mi][3], aAhi + off);
                LDSM_X4(al[mi][0], al[mi][1], al[mi][2], al[mi][3], aAlo + off);
            }
            uint32_t b[8][2];
            int g = lane >> 3;
            #pragma unroll
            for (int p = 0; p < 4; p++) {
                int nrow = warp_n * 64 + p * 16 + (g >> 1) * 8 + (lane & 7);
                int col = kk + (g & 1) * 8;
                uint32_t off = (uint32_t)(nrow * SKEW + col) * 2;
                uint32_t r0, r1, r2, r3;
                LDSM_X4(r0, r1, r2, r3, aBhi + off);
                b[p * 2][0] = r0; b[p * 2][1] = r1;
                b[p * 2 + 1][0] = r2; b[p * 2 + 1][1] = r3;
            }
            #pragma unroll
            for (int mi = 0; mi < 2; mi++)
                #pragma unroll
                for (int ni = 0; ni < 8; ni++) {
                    MMA16816(acc[mi][ni], ah[mi], b[ni]);
                    MMA16816(acc[mi][ni], al[mi], b[ni]);
                }
            #pragma unroll
            for (int p = 0; p < 4; p++) {
                int nrow = warp_n * 64 + p * 16 + (g >> 1) * 8 + (lane & 7);
                int col = kk + (g & 1) * 8;
                uint32_t off = (uint32_t)(nrow * SKEW + col) * 2;
                uint32_t r0, r1, r2, r3;
                LDSM_X4(r0, r1, r2, r3, aBlo + off);
                b[p * 2][0] = r0; b[p * 2][1] = r1;
                b[p * 2 + 1][0] = r2; b[p * 2 + 1][1] = r3;
            }
            #pragma unroll
            for (int mi = 0; mi < 2; mi++)
                #pragma unroll
                for (int ni = 0; ni < 8; ni++)
                    MMA16816(acc[mi][ni], ah[mi], b[ni]);
        }
        __syncthreads();
    }

    // epilogue
    int gid = lane >> 2, tig = lane & 3;
    #pragma unroll
    for (int mi = 0; mi < 2; mi++) {
        #pragma unroll
        for (int ni = 0; ni < 8; ni++) {
            int col = warp_n * 64 + ni * 8 + tig * 2;
            int r0 = m0 + warp_m * 32 + mi * 16 + gid;
            if (r0 < M)
                *(float2*)(g_h + (size_t)r0 * 128 + col) =
                    make_float2(acc[mi][ni][0], acc[mi][ni][1]);
            int r1 = r0 + 8;
            if (r1 < M)
                *(float2*)(g_h + (size_t)r1 * 128 + col) =
                    make_float2(acc[mi][ni][2], acc[mi][ni][3]);
        }
    }
}

// ---------------- SIMT SGEMM (classifier only, N=40) ----------------
__device__ __forceinline__ void sgemm_body(
    const float* __restrict__ A, const float* __restrict__ B,
    const float* __restrict__ bias, float* __restrict__ C, int M, int N, int K) {
    const int BM = 64, BN = 64, BK = 16, TM = 4, TN = 4;
    __shared__ float As[BK][BM + 4];
    __shared__ float Bs[BK][BN];
    int tid = threadIdx.x;
    int tx = tid % 16, ty = tid / 16;
    int rowBlock = blockIdx.x * BM, colBlock = blockIdx.y * BN;
    float acc[TM][TN] = {};
    int aR = tid >> 2, aC = (tid & 3) * 4;
    int bR = tid >> 4, bC = (tid & 15) * 4;
    for (int k0 = 0; k0 < K; k0 += BK) {
        int gr = rowBlock + aR;
        float4 av = make_float4(0.f, 0.f, 0.f, 0.f);
        if (gr < M) av = *(const float4*)(A + (size_t)gr * K + k0 + aC);
        As[aC + 0][aR] = av.x; As[aC + 1][aR] = av.y;
        As[aC + 2][aR] = av.z; As[aC + 3][aR] = av.w;
        int gc = colBlock + bC;
        float4 bv;
        if (gc + 3 < N) {
            bv = *(const float4*)(B + (size_t)(k0 + bR) * N + gc);
        } else {
            float t0 = (gc + 0 < N) ? B[(size_t)(k0 + bR) * N + gc + 0] : 0.f;
            float t1 = (gc + 1 < N) ? B[(size_t)(k0 + bR) * N + gc + 1] : 0.f;
            float t2 = (gc + 2 < N) ? B[(size_t)(k0 + bR) * N + gc + 2] : 0.f;
            float t3 = (gc + 3 < N) ? B[(size_t)(k0 + bR) * N + gc + 3] : 0.f;
            bv = make_float4(t0, t1, t2, t3);
        }
        *(float4*)&Bs[bR][bC] = bv;
        __syncthreads();
        #pragma unroll
        for (int k = 0; k < BK; k++) {
            float4 ra = *(const float4*)&As[k][ty * TM];
            float4 rb = *(const float4*)&Bs[k][tx * TN];
            float a0[4] = {ra.x, ra.y, ra.z, ra.w};
            float b0[4] = {rb.x, rb.y, rb.z, rb.w};
            #pragma unroll
            for (int i = 0; i < 4; i++)
                #pragma unroll
                for (int j = 0; j < 4; j++)
                    acc[i][j] += a0[i] * b0[j];
        }
        __syncthreads();
    }
    #pragma unroll
    for (int i = 0; i < TM; i++) {
        int m = rowBlock + ty * TM + i;
        if (m >= M) continue;
        #pragma unroll
        for (int j = 0; j < TN; j++) {
            int nn = colBlock + tx * TN + j;
            if (nn >= N) continue;
            float v = acc[i][j];
            if (bias) v += bias[nn];
            C[(size_t)m * N + nn] = v;
        }
    }
}
__global__ void sgemm_a_wc(const float* __restrict__ B, const float* __restrict__ bias,
                           float* __restrict__ C, int M, int N, int K) {
    sgemm_body(g_a, B, bias, C, M, N, K);
}

// ---------------- aggregation: warp per node, 2-way ILP ----------------
// r = relu( sum_e w_e*h[src_e] + dinv^2*h[i] + bias )
// mode 0: write bf16 hi/lo (feeds next GEMM);  mode 1: write fp32 g_a.
__global__ void agg_kernel(const float* __restrict__ bias, int n, int mode) {
    int warp = (blockIdx.x * blockDim.x + threadIdx.x) >> 5;
    if (warp >= n) return;
    int lane = threadIdx.x & 31;
    int beg = g_rowptr[warp], end = g_rowptr[warp + 1];
    const float4* hv = (const float4*)g_h;

    float4 acc0 = make_float4(0.f, 0.f, 0.f, 0.f);
    float4 acc1 = make_float4(0.f, 0.f, 0.f, 0.f);
    int e = beg;
    for (; e + 2 <= end; e += 2) {
        int s0 = g_col[e], s1 = g_col[e + 1];
        float w0 = g_w[e], w1 = g_w[e + 1];
        float4 v0 = hv[(size_t)s0 * 32 + lane];
        float4 v1 = hv[(size_t)s1 * 32 + lane];
        acc0.x += w0 * v0.x; acc0.y += w0 * v0.y;
        acc0.z += w0 * v0.z; acc0.w += w0 * v0.w;
        acc1.x += w1 * v1.x; acc1.y += w1 * v1.y;
        acc1.z += w1 * v1.z; acc1.w += w1 * v1.w;
    }
    if (e < end) {
        int s0 = g_col[e];
        float w0 = g_w[e];
        float4 v0 = hv[(size_t)s0 * 32 + lane];
        acc0.x += w0 * v0.x; acc0.y += w0 * v0.y;
        acc0.z += w0 * v0.z; acc0.w += w0 * v0.w;
    }
    acc0.x += acc1.x; acc0.y += acc1.y; acc0.z += acc1.z; acc0.w += acc1.w;

    float di = g_dinv[warp], di2 = di * di;
    float4 hs = hv[(size_t)warp * 32 + lane];
    float4 bb = ((const float4*)bias)[lane];
    float4 r;
    r.x = fmaxf(acc0.x + di2 * hs.x + bb.x, 0.f);
    r.y = fmaxf(acc0.y + di2 * hs.y + bb.y, 0.f);
    r.z = fmaxf(acc0.z + di2 * hs.z + bb.z, 0.f);
    r.w = fmaxf(acc0.w + di2 * hs.w + bb.w, 0.f);

    if (mode == 1) {
        ((float4*)g_a)[(size_t)warp * 32 + lane] = r;
    } else {
        // split to bf16 hi/lo, 8B stores
        __nv_bfloat16 h0 = __float2bfloat16(r.x), h1 = __float2bfloat16(r.y);
        __nv_bfloat16 h2 = __float2bfloat16(r.z), h3 = __float2bfloat16(r.w);
        __nv_bfloat16 l0 = __float2bfloat16(r.x - __bfloat162float(h0));
        __nv_bfloat16 l1 = __float2bfloat16(r.y - __bfloat162float(h1));
        __nv_bfloat16 l2 = __float2bfloat16(r.z - __bfloat162float(h2));
        __nv_bfloat16 l3 = __float2bfloat16(r.w - __bfloat162float(h3));
        __nv_bfloat162 hp0; hp0.x = h0; hp0.y = h1;
        __nv_bfloat162 hp1; hp1.x = h2; hp1.y = h3;
        __nv_bfloat162 lp0; lp0.x = l0; lp0.y = l1;
        __nv_bfloat162 lp1; lp1.x = l2; lp1.y = l3;
        size_t idx2 = (size_t)warp * 64 + lane * 2;   // bfloat162 index
        ((__nv_bfloat162*)g_Ahi)[idx2] = hp0;
        ((__nv_bfloat162*)g_Ahi)[idx2 + 1] = hp1;
        ((__nv_bfloat162*)g_Alo)[idx2] = lp0;
        ((__nv_bfloat162*)g_Alo)[idx2 + 1] = lp1;
    }
}

// ---------------- launch ----------------
extern "C" void kernel_launch(void* const* d_in, const int* in_sizes, int n_in,
                              void* d_out, int out_size) {
    const float* x  = (const float*)d_in[0];
    const void*  ei = d_in[1];
    const float* W1 = (const float*)d_in[2];
    const float* b1 = (const float*)d_in[3];
    const float* W2 = (const float*)d_in[4];
    const float* b2 = (const float*)d_in[5];
    const float* Wc = (const float*)d_in[6];
    const float* bc = (const float*)d_in[7];
    float*       out = (float*)d_out;

    const int n = in_sizes[0] / F0;   // 100000
    const int E = in_sizes[1] / 2;    // 1600000

    cudaFuncSetAttribute(mma_gemm, cudaFuncAttributeMaxDynamicSharedMemorySize, GSM_TOTAL);

    // ---- dtype detect + graph preprocessing ----
    detect_kernel<<<1, 256>>>((const int*)ei, 2 * E);
    zero_kernel<<<(n + 255) / 256, 256>>>(n);
    int gbE = (E + 255) / 256;
    deg_kernel<<<gbE, 256>>>(ei, E);
    dinv_kernel<<<(n + 255) / 256, 256>>>(n);
    scan_kernel<<<1, 1024>>>(n);
    scatter_kernel<<<gbE, 256>>>(ei, E);

    // ---- weight prep ----
    split_wt<<<(F0 * FH + 255) / 256, 256>>>(W1, F0, 1);
    split_wt<<<(FH * FH + 255) / 256, 256>>>(W2, FH, 2);

    int mBlocks = (n + 127) / 128;

    // ---- layer 1 ----
    split_src<<<(n * F0 + 255) / 256, 256>>>(x, n * F0);
    mma_gemm<<<mBlocks, 256, GSM_TOTAL>>>(1, n, F0);
    agg_kernel<<<(n + 7) / 8, 256>>>(b1, n, 0);   // -> bf16 hi/lo

    // ---- layer 2 ----
    mma_gemm<<<mBlocks, 256, GSM_TOTAL>>>(2, n, FH);
    agg_kernel<<<(n + 7) / 8, 256>>>(b2, n, 1);   // -> fp32 g_a

    // ---- classifier (fp32 SIMT) ----
    dim3 gridc((n + 63) / 64, (FC + 63) / 64);
    sgemm_a_wc<<<gridc, 256>>>(Wc, bc, out, n, FC, FH);
}

// round 8
// speedup vs baseline: 1.3642x; 1.1543x over previous
#include <cuda_runtime.h>
#include <cuda_bf16.h>
#include <cstdint>

#define NN 100000
#define EE 1600000
#define F0 256
#define FH 128
#define FC 40

// ---------------- static device scratch ----------------
__device__ float g_h[(size_t)NN * FH];
__device__ float g_a[(size_t)NN * FH];
__device__ int   g_deg[NN];
__device__ int   g_cur[NN];
__device__ float g_dinv[NN];
__device__ int   g_rowptr[NN + 1];
__device__ int   g_col[EE];
__device__ float g_w[EE];                 // dinv[src]*dinv[dst] per CSR slot
__device__ int   g_is64;
__device__ __nv_bfloat16 g_Ahi[(size_t)NN * F0];
__device__ __nv_bfloat16 g_Alo[(size_t)NN * F0];
__device__ __nv_bfloat16 g_W1thi[FH * F0], g_W1tlo[FH * F0];   // [N=128][K] K-major
__device__ __nv_bfloat16 g_W2thi[FH * FH], g_W2tlo[FH * FH];

// ---------------- helpers ----------------
__device__ __forceinline__ uint32_t smem_u32(const void* p) {
    uint32_t a;
    asm("{ .reg .u64 t; cvta.to.shared.u64 t, %1; cvt.u32.u64 %0, t; }" : "=r"(a) : "l"(p));
    return a;
}
#define LDSM_X4(r0, r1, r2, r3, addr) \
    asm volatile("ldmatrix.sync.aligned.m8n8.x4.shared.b16 {%0,%1,%2,%3}, [%4];" \
                 : "=r"(r0), "=r"(r1), "=r"(r2), "=r"(r3) : "r"(addr))
#define MMA16816(d, a, b) \
    asm volatile("mma.sync.aligned.m16n8k16.row.col.f32.bf16.bf16.f32 " \
                 "{%0,%1,%2,%3}, {%4,%5,%6,%7}, {%8,%9}, {%0,%1,%2,%3};" \
                 : "+f"((d)[0]), "+f"((d)[1]), "+f"((d)[2]), "+f"((d)[3]) \
                 : "r"((a)[0]), "r"((a)[1]), "r"((a)[2]), "r"((a)[3]), \
                   "r"((b)[0]), "r"((b)[1]))
#define CP_ASYNC16(dst, src, sz) \
    asm volatile("cp.async.cg.shared.global [%0], [%1], 16, %2;" \
                 :: "r"(dst), "l"(src), "r"(sz) : "memory")
#define CP_COMMIT asm volatile("cp.async.commit_group;" ::: "memory")
#define CP_WAIT(n) asm volatile("cp.async.wait_group %0;" :: "n"(n) : "memory")

__device__ __forceinline__ int load_edge(const void* ei, long long idx, int is64) {
    if (is64) return (int)((const long long*)ei)[idx];
    return ((const int*)ei)[idx];
}
__device__ __forceinline__ void split1(float f, __nv_bfloat16& hi, __nv_bfloat16& lo) {
    hi = __float2bfloat16(f);
    lo = __float2bfloat16(f - __bfloat162float(hi));
}

// ================= K0: detect dtype (block 0) + zero counters =================
__global__ void k0_detect_zero(const int* __restrict__ ei32, int total_words, int n) {
    if (blockIdx.x == 0) {
        __shared__ int acc;
        if (threadIdx.x == 0) acc = 0;
        __syncthreads();
        int v = 0;
        int lim = min(total_words, 8192);
        for (int i = 1 + 2 * threadIdx.x; i < lim; i += 2 * blockDim.x) v |= ei32[i];
        if (v) atomicOr(&acc, 1);
        __syncthreads();
        if (threadIdx.x == 0) g_is64 = (acc == 0) ? 1 : 0;
    } else {
        int i = (blockIdx.x - 1) * blockDim.x + threadIdx.x;
        if (i < n) { g_deg[i] = 0; g_cur[i] = 0; }
    }
}

// ============ K1: deg histogram ∥ split_src ∥ split_wt1 ∥ split_wt2 ==========
__global__ void k1_prep(const void* __restrict__ ei, int E,
                        const float* __restrict__ x,
                        const float* __restrict__ W1, const float* __restrict__ W2,
                        int n, int bDeg, int bSplit, int bW1) {
    int b = blockIdx.x, tid = threadIdx.x;
    if (b < bDeg) {
        // degree histogram, 4 edges/thread
        int is64 = g_is64;
        int base = (b * 256 + tid) * 4;
        #pragma unroll
        for (int j = 0; j < 4; j++) {
            int i = base + j;
            if (i < E) {
                int d = load_edge(ei, (long long)E + i, is64);
                if ((unsigned)d < (unsigned)NN) atomicAdd(&g_deg[d], 1);
            }
        }
    } else if (b < bDeg + bSplit) {
        // split x -> bf16 hi/lo, one float4 per thread
        int id = (b - bDeg) * 256 + tid;
        int nf4 = n * F0 / 4;
        if (id < nf4) {
            float4 v = ((const float4*)x)[id];
            __nv_bfloat16 h0, h1, h2, h3, l0, l1, l2, l3;
            split1(v.x, h0, l0); split1(v.y, h1, l1);
            split1(v.z, h2, l2); split1(v.w, h3, l3);
            __nv_bfloat162 hp0; hp0.x = h0; hp0.y = h1;
            __nv_bfloat162 hp1; hp1.x = h2; hp1.y = h3;
            __nv_bfloat162 lp0; lp0.x = l0; lp0.y = l1;
            __nv_bfloat162 lp1; lp1.x = l2; lp1.y = l3;
            ((__nv_bfloat162*)g_Ahi)[id * 2] = hp0;
            ((__nv_bfloat162*)g_Ahi)[id * 2 + 1] = hp1;
            ((__nv_bfloat162*)g_Alo)[id * 2] = lp0;
            ((__nv_bfloat162*)g_Alo)[id * 2 + 1] = lp1;
        }
    } else if (b < bDeg + bSplit + bW1) {
        // W1[K=256,N=128] -> Wt hi/lo
        int i = (b - bDeg - bSplit) * 256 + tid;
        if (i < F0 * FH) {
            int k = i / FH, nidx = i % FH;
            __nv_bfloat16 hi, lo;
            split1(W1[i], hi, lo);
            g_W1thi[nidx * F0 + k] = hi;
            g_W1tlo[nidx * F0 + k] = lo;
        }
    } else {
        int i = (b - bDeg - bSplit - bW1) * 256 + tid;
        if (i < FH * FH) {
            int k = i / FH, nidx = i % FH;
            __nv_bfloat16 hi, lo;
            split1(W2[i], hi, lo);
            g_W2thi[nidx * FH + k] = hi;
            g_W2tlo[nidx * FH + k] = lo;
        }
    }
}

// ============ GEMM device body (mma.sync bf16, cp.async 2-stage) =============
// BM=128 BN=128 BK=32, 8 warps (4xM, 2xN), warp tile 32x64, 3-term split.
#define SKEW 40
#define TILE_B (128 * SKEW * 2)
#define STAGE_B (4 * TILE_B)
#define GSM_TOTAL (2 * STAGE_B)     // 81920 bytes

__device__ __forceinline__ void gemm_load_stage(
    uint32_t sbase, const __nv_bfloat16* __restrict__ Ah, const __nv_bfloat16* __restrict__ Al,
    const __nv_bfloat16* __restrict__ Bh, const __nv_bfloat16* __restrict__ Bl,
    int m0, int kc, int K, int M)
{
    int tid = threadIdx.x;
    #pragma unroll
    for (int it = 0; it < 2; it++) {
        int id = it * 256 + tid;
        int row = id >> 2, seg = id & 3;
        uint32_t soff = (uint32_t)(row * SKEW + seg * 8) * 2;
        int gr = m0 + row;
        int ok = (gr < M) ? 16 : 0;
        size_t grc = (gr < M) ? (size_t)gr : 0;
        CP_ASYNC16(sbase + soff,               Ah + grc * K + kc + seg * 8, ok);
        CP_ASYNC16(sbase + TILE_B + soff,      Al + grc * K + kc + seg * 8, ok);
        CP_ASYNC16(sbase + 2 * TILE_B + soff,  Bh + (size_t)row * K + kc + seg * 8, 16);
        CP_ASYNC16(sbase + 3 * TILE_B + soff,  Bl + (size_t)row * K + kc + seg * 8, 16);
    }
}

__device__ void mma_gemm_dev(char* smem, int bidx, int layer, int M, int K) {
    uint32_t sb = smem_u32(smem);
    const __nv_bfloat16* Bh = (layer == 1) ? g_W1thi : g_W2thi;
    const __nv_bfloat16* Bl = (layer == 1) ? g_W1tlo : g_W2tlo;

    int tid = threadIdx.x, wid = tid >> 5, lane = tid & 31;
    int m0 = bidx * 128;
    int warp_m = wid & 3, warp_n = wid >> 2;

    float acc[2][8][4] = {};

    int nch = K >> 5;
    gemm_load_stage(sb, g_Ahi, g_Alo, Bh, Bl, m0, 0, K, M);
    CP_COMMIT;

    for (int c = 0; c < nch; c++) {
        if (c + 1 < nch) {
            gemm_load_stage(sb + ((c + 1) & 1) * STAGE_B, g_Ahi, g_Alo, Bh, Bl,
                            m0, (c + 1) << 5, K, M);
            CP_COMMIT;
            CP_WAIT(1);
        } else {
            CP_WAIT(0);
        }
        __syncthreads();

        uint32_t stg = sb + (c & 1) * STAGE_B;
        uint32_t aAhi = stg, aAlo = stg + TILE_B;
        uint32_t aBhi = stg + 2 * TILE_B, aBlo = stg + 3 * TILE_B;

        #pragma unroll
        for (int kk = 0; kk < 32; kk += 16) {
            uint32_t ah[2][4], al[2][4];
            #pragma unroll
            for (int mi = 0; mi < 2; mi++) {
                int row = warp_m * 32 + mi * 16 + (lane & 15);
                int col = kk + (lane >> 4) * 8;
                uint32_t off = (uint32_t)(row * SKEW + col) * 2;
                LDSM_X4(ah[mi][0], ah[mi][1], ah[mi][2], ah[mi][3], aAhi + off);
                LDSM_X4(al[mi][0], al[mi][1], al[mi][2], al[mi][3], aAlo + off);
            }
            uint32_t b[8][2];
            int g = lane >> 3;
            #pragma unroll
            for (int p = 0; p < 4; p++) {
                int nrow = warp_n * 64 + p * 16 + (g >> 1) * 8 + (lane & 7);
                int col = kk + (g & 1) * 8;
                uint32_t off = (uint32_t)(nrow * SKEW + col) * 2;
                uint32_t r0, r1, r2, r3;
                LDSM_X4(r0, r1, r2, r3, aBhi + off);
                b[p * 2][0] = r0; b[p * 2][1] = r1;
                b[p * 2 + 1][0] = r2; b[p * 2 + 1][1] = r3;
            }
            #pragma unroll
            for (int mi = 0; mi < 2; mi++)
                #pragma unroll
                for (int ni = 0; ni < 8; ni++) {
                    MMA16816(acc[mi][ni], ah[mi], b[ni]);
                    MMA16816(acc[mi][ni], al[mi], b[ni]);
                }
            #pragma unroll
            for (int p = 0; p < 4; p++) {
                int nrow = warp_n * 64 + p * 16 + (g >> 1) * 8 + (lane & 7);
                int col = kk + (g & 1) * 8;
                uint32_t off = (uint32_t)(nrow * SKEW + col) * 2;
                uint32_t r0, r1, r2, r3;
                LDSM_X4(r0, r1, r2, r3, aBlo + off);
                b[p * 2][0] = r0; b[p * 2][1] = r1;
                b[p * 2 + 1][0] = r2; b[p * 2 + 1][1] = r3;
            }
            #pragma unroll
            for (int mi = 0; mi < 2; mi++)
                #pragma unroll
                for (int ni = 0; ni < 8; ni++)
                    MMA16816(acc[mi][ni], ah[mi], b[ni]);
        }
        __syncthreads();
    }

    int gid = lane >> 2, tig = lane & 3;
    #pragma unroll
    for (int mi = 0; mi < 2; mi++) {
        #pragma unroll
        for (int ni = 0; ni < 8; ni++) {
            int col = warp_n * 64 + ni * 8 + tig * 2;
            int r0 = m0 + warp_m * 32 + mi * 16 + gid;
            if (r0 < M)
                *(float2*)(g_h + (size_t)r0 * 128 + col) =
                    make_float2(acc[mi][ni][0], acc[mi][ni][1]);
            int r1 = r0 + 8;
            if (r1 < M)
                *(float2*)(g_h + (size_t)r1 * 128 + col) =
                    make_float2(acc[mi][ni][2], acc[mi][ni][3]);
        }
    }
}

// ============ K2: GEMM-1 ∥ exclusive scan (1 block) ∥ dinv ====================
__global__ void __launch_bounds__(256, 2) k2_gemm1_scan_dinv(int M, int n, int gemmB) {
    extern __shared__ char smem[];
    int b = blockIdx.x;
    if (b < gemmB) {
        mma_gemm_dev(smem, b, 1, M, F0);
    } else if (b == gemmB) {
        // 256-thread exclusive scan of g_deg -> g_rowptr
        __shared__ int sh[256];
        int tid = threadIdx.x;
        int chunk = (n + 255) >> 8;
        int start = tid * chunk, end = min(start + chunk, n);
        int sum = 0;
        for (int i = start; i < end; i++) sum += g_deg[i];
        sh[tid] = sum;
        __syncthreads();
        for (int off = 1; off < 256; off <<= 1) {
            int v = 0;
            if (tid >= off) v = sh[tid - off];
            __syncthreads();
            sh[tid] += v;
            __syncthreads();
        }
        int run = sh[tid] - sum;
        for (int i = start; i < end; i++) { g_rowptr[i] = run; run += g_deg[i]; }
        if (end == n) g_rowptr[n] = run;
    } else {
        int i = (b - gemmB - 1) * 256 + threadIdx.x;
        if (i < n) g_dinv[i] = rsqrtf((float)g_deg[i] + 1.0f);
    }
}

__global__ void __launch_bounds__(256, 2) mma_gemm2(int M) {
    extern __shared__ char smem[];
    mma_gemm_dev(smem, blockIdx.x, 2, M, FH);
}

// ============ K3: CSR scatter ================================================
__global__ void k3_scatter(const void* __restrict__ ei, int E) {
    int is64 = g_is64;
    int base = (blockIdx.x * 256 + threadIdx.x) * 4;
    #pragma unroll
    for (int j = 0; j < 4; j++) {
        int i = base + j;
        if (i >= E) break;
        int s = load_edge(ei, i, is64);
        int d = load_edge(ei, (long long)E + i, is64);
        if ((unsigned)s >= (unsigned)NN || (unsigned)d >= (unsigned)NN) continue;
        int pos = g_rowptr[d] + atomicAdd(&g_cur[d], 1);
        g_col[pos] = s;
        g_w[pos]   = g_dinv[s] * g_dinv[d];
    }
}

// ---------------- aggregation: warp per node, 2-way ILP ----------------
__global__ void agg_kernel(const float* __restrict__ bias, int n, int mode) {
    int warp = (blockIdx.x * blockDim.x + threadIdx.x) >> 5;
    if (warp >= n) return;
    int lane = threadIdx.x & 31;
    int beg = g_rowptr[warp], end = g_rowptr[warp + 1];
    const float4* hv = (const float4*)g_h;

    float4 acc0 = make_float4(0.f, 0.f, 0.f, 0.f);
    float4 acc1 = make_float4(0.f, 0.f, 0.f, 0.f);
    int e = beg;
    for (; e + 2 <= end; e += 2) {
        int s0 = g_col[e], s1 = g_col[e + 1];
        float w0 = g_w[e], w1 = g_w[e + 1];
        float4 v0 = hv[(size_t)s0 * 32 + lane];
        float4 v1 = hv[(size_t)s1 * 32 + lane];
        acc0.x += w0 * v0.x; acc0.y += w0 * v0.y;
        acc0.z += w0 * v0.z; acc0.w += w0 * v0.w;
        acc1.x += w1 * v1.x; acc1.y += w1 * v1.y;
        acc1.z += w1 * v1.z; acc1.w += w1 * v1.w;
    }
    if (e < end) {
        int s0 = g_col[e];
        float w0 = g_w[e];
        float4 v0 = hv[(size_t)s0 * 32 + lane];
        acc0.x += w0 * v0.x; acc0.y += w0 * v0.y;
        acc0.z += w0 * v0.z; acc0.w += w0 * v0.w;
    }
    acc0.x += acc1.x; acc0.y += acc1.y; acc0.z += acc1.z; acc0.w += acc1.w;

    float di = g_dinv[warp], di2 = di * di;
    float4 hs = hv[(size_t)warp * 32 + lane];
    float4 bb = ((const float4*)bias)[lane];
    float4 r;
    r.x = fmaxf(acc0.x + di2 * hs.x + bb.x, 0.f);
    r.y = fmaxf(acc0.y + di2 * hs.y + bb.y, 0.f);
    r.z = fmaxf(acc0.z + di2 * hs.z + bb.z, 0.f);
    r.w = fmaxf(acc0.w + di2 * hs.w + bb.w, 0.f);

    if (mode == 1) {
        ((float4*)g_a)[(size_t)warp * 32 + lane] = r;
    } else {
        __nv_bfloat16 h0, h1, h2, h3, l0, l1, l2, l3;
        split1(r.x, h0, l0); split1(r.y, h1, l1);
        split1(r.z, h2, l2); split1(r.w, h3, l3);
        __nv_bfloat162 hp0; hp0.x = h0; hp0.y = h1;
        __nv_bfloat162 hp1; hp1.x = h2; hp1.y = h3;
        __nv_bfloat162 lp0; lp0.x = l0; lp0.y = l1;
        __nv_bfloat162 lp1; lp1.x = l2; lp1.y = l3;
        size_t idx2 = (size_t)warp * 64 + lane * 2;
        ((__nv_bfloat162*)g_Ahi)[idx2] = hp0;
        ((__nv_bfloat162*)g_Ahi)[idx2 + 1] = hp1;
        ((__nv_bfloat162*)g_Alo)[idx2] = lp0;
        ((__nv_bfloat162*)g_Alo)[idx2 + 1] = lp1;
    }
}

// ---------------- SIMT SGEMM (classifier, N=40) ----------------
__global__ void sgemm_a_wc(const float* __restrict__ B, const float* __restrict__ bias,
                           float* __restrict__ C, int M, int N, int K) {
    const int BM = 64, BN = 64, BK = 16, TM = 4, TN = 4;
    __shared__ float As[BK][BM + 4];
    __shared__ float Bs[BK][BN];
    const float* A = g_a;
    int tid = threadIdx.x;
    int tx = tid % 16, ty = tid / 16;
    int rowBlock = blockIdx.x * BM, colBlock = blockIdx.y * BN;
    float acc[TM][TN] = {};
    int aR = tid >> 2, aC = (tid & 3) * 4;
    int bR = tid >> 4, bC = (tid & 15) * 4;
    for (int k0 = 0; k0 < K; k0 += BK) {
        int gr = rowBlock + aR;
        float4 av = make_float4(0.f, 0.f, 0.f, 0.f);
        if (gr < M) av = *(const float4*)(A + (size_t)gr * K + k0 + aC);
        As[aC + 0][aR] = av.x; As[aC + 1][aR] = av.y;
        As[aC + 2][aR] = av.z; As[aC + 3][aR] = av.w;
        int gc = colBlock + bC;
        float4 bv;
        if (gc + 3 < N) {
            bv = *(const float4*)(B + (size_t)(k0 + bR) * N + gc);
        } else {
            float t0 = (gc + 0 < N) ? B[(size_t)(k0 + bR) * N + gc + 0] : 0.f;
            float t1 = (gc + 1 < N) ? B[(size_t)(k0 + bR) * N + gc + 1] : 0.f;
            float t2 = (gc + 2 < N) ? B[(size_t)(k0 + bR) * N + gc + 2] : 0.f;
            float t3 = (gc + 3 < N) ? B[(size_t)(k0 + bR) * N + gc + 3] : 0.f;
            bv = make_float4(t0, t1, t2, t3);
        }
        *(float4*)&Bs[bR][bC] = bv;
        __syncthreads();
        #pragma unroll
        for (int k = 0; k < BK; k++) {
            float4 ra = *(const float4*)&As[k][ty * TM];
            float4 rb = *(const float4*)&Bs[k][tx * TN];
            float a0[4] = {ra.x, ra.y, ra.z, ra.w};
            float b0[4] = {rb.x, rb.y, rb.z, rb.w};
            #pragma unroll
            for (int i = 0; i < 4; i++)
                #pragma unroll
                for (int j = 0; j < 4; j++)
                    acc[i][j] += a0[i] * b0[j];
        }
        __syncthreads();
    }
    #pragma unroll
    for (int i = 0; i < TM; i++) {
        int m = rowBlock + ty * TM + i;
        if (m >= M) continue;
        #pragma unroll
        for (int j = 0; j < TN; j++) {
            int nn = colBlock + tx * TN + j;
            if (nn >= N) continue;
            float v = acc[i][j];
            if (bias) v += bias[nn];
            C[(size_t)m * N + nn] = v;
        }
    }
}

// ---------------- launch ----------------
extern "C" void kernel_launch(void* const* d_in, const int* in_sizes, int n_in,
                              void* d_out, int out_size) {
    const float* x  = (const float*)d_in[0];
    const void*  ei = d_in[1];
    const float* W1 = (const float*)d_in[2];
    const float* b1 = (const float*)d_in[3];
    const float* W2 = (const float*)d_in[4];
    const float* b2 = (const float*)d_in[5];
    const float* Wc = (const float*)d_in[6];
    const float* bc = (const float*)d_in[7];
    float*       out = (float*)d_out;

    const int n = in_sizes[0] / F0;   // 100000
    const int E = in_sizes[1] / 2;    // 1600000

    cudaFuncSetAttribute(k2_gemm1_scan_dinv, cudaFuncAttributeMaxDynamicSharedMemorySize, GSM_TOTAL);
    cudaFuncSetAttribute(mma_gemm2, cudaFuncAttributeMaxDynamicSharedMemorySize, GSM_TOTAL);

    int zB    = (n + 255) / 256;              // 391
    int bDeg  = (E + 1023) / 1024;            // 1563
    int bSplit = (n * F0 / 4 + 255) / 256;    // 25000
    int bW1   = (F0 * FH + 255) / 256;        // 128
    int bW2   = (FH * FH + 255) / 256;        // 64
    int gemmB = (n + 127) / 128;              // 782
    int dinvB = (n + 255) / 256;              // 391

    // K0: detect ∥ zero
    k0_detect_zero<<<1 + zB, 256>>>((const int*)ei, 2 * E, n);
    // K1: deg ∥ split_src ∥ split_wt1 ∥ split_wt2
    k1_prep<<<bDeg + bSplit + bW1 + bW2, 256>>>(ei, E, x, W1, W2, n, bDeg, bSplit, bW1);
    // K2: gemm1 ∥ scan ∥ dinv
    k2_gemm1_scan_dinv<<<gemmB + 1 + dinvB, 256, GSM_TOTAL>>>(n, n, gemmB);
    // K3: scatter
    k3_scatter<<<(E + 1023) / 1024, 256>>>(ei, E);
    // agg1 -> bf16 hi/lo
    agg_kernel<<<(n + 7) / 8, 256>>>(b1, n, 0);
    // gemm2
    mma_gemm2<<<gemmB, 256, GSM_TOTAL>>>(n);
    // agg2 -> fp32
    agg_kernel<<<(n + 7) / 8, 256>>>(b2, n, 1);
    // classifier
    dim3 gridc((n + 63) / 64, (FC + 63) / 64);
    sgemm_a_wc<<<gridc, 256>>>(Wc, bc, out, n, FC, FH);
}

// round 9
// speedup vs baseline: 1.4182x; 1.0395x over previous
#include <cuda_runtime.h>
#include <cuda_bf16.h>
#include <cstdint>

#define NN 100000
#define EE 1600000
#define F0 256
#define FH 128
#define FC 40

// ---------------- static device scratch ----------------
__device__ float g_h[(size_t)NN * FH];
__device__ int   g_deg[NN];
__device__ float g_dinv[NN];
__device__ int   g_rowptr[NN + 1];
__device__ int   g_col[EE];
__device__ int   g_slot[EE];              // per-edge slot within dst row (from deg atomics)
__device__ float g_w[EE];                 // dinv[src]*dinv[dst] per CSR slot
__device__ int   g_is64;
__device__ __nv_bfloat16 g_Ahi[(size_t)NN * F0];
__device__ __nv_bfloat16 g_Alo[(size_t)NN * F0];
__device__ __nv_bfloat16 g_W1thi[FH * F0], g_W1tlo[FH * F0];   // [128][256] K-major
__device__ __nv_bfloat16 g_W2thi[FH * FH], g_W2tlo[FH * FH];   // [128][128] K-major
__device__ __nv_bfloat16 g_Wcthi[64 * FH], g_Wctlo[64 * FH];   // [64(pad 40)][128] K-major

// ---------------- helpers ----------------
__device__ __forceinline__ uint32_t smem_u32(const void* p) {
    uint32_t a;
    asm("{ .reg .u64 t; cvta.to.shared.u64 t, %1; cvt.u32.u64 %0, t; }" : "=r"(a) : "l"(p));
    return a;
}
#define LDSM_X4(r0, r1, r2, r3, addr) \
    asm volatile("ldmatrix.sync.aligned.m8n8.x4.shared.b16 {%0,%1,%2,%3}, [%4];" \
                 : "=r"(r0), "=r"(r1), "=r"(r2), "=r"(r3) : "r"(addr))
#define MMA16816(d, a, b) \
    asm volatile("mma.sync.aligned.m16n8k16.row.col.f32.bf16.bf16.f32 " \
                 "{%0,%1,%2,%3}, {%4,%5,%6,%7}, {%8,%9}, {%0,%1,%2,%3};" \
                 : "+f"((d)[0]), "+f"((d)[1]), "+f"((d)[2]), "+f"((d)[3]) \
                 : "r"((a)[0]), "r"((a)[1]), "r"((a)[2]), "r"((a)[3]), \
                   "r"((b)[0]), "r"((b)[1]))
#define CP_ASYNC16(dst, src, sz) \
    asm volatile("cp.async.cg.shared.global [%0], [%1], 16, %2;" \
                 :: "r"(dst), "l"(src), "r"(sz) : "memory")
#define CP_COMMIT asm volatile("cp.async.commit_group;" ::: "memory")
#define CP_WAIT(n) asm volatile("cp.async.wait_group %0;" :: "n"(n) : "memory")

__device__ __forceinline__ int load_edge(const void* ei, long long idx, int is64) {
    if (is64) return (int)((const long long*)ei)[idx];
    return ((const int*)ei)[idx];
}
__device__ __forceinline__ void split1(float f, __nv_bfloat16& hi, __nv_bfloat16& lo) {
    hi = __float2bfloat16(f);
    lo = __float2bfloat16(f - __bfloat162float(hi));
}

// ================= K0: detect dtype (block 0) + zero deg =====================
__global__ void k0_detect_zero(const int* __restrict__ ei32, int total_words, int n) {
    if (blockIdx.x == 0) {
        __shared__ int acc;
        if (threadIdx.x == 0) acc = 0;
        __syncthreads();
        int v = 0;
        int lim = min(total_words, 8192);
        for (int i = 1 + 2 * threadIdx.x; i < lim; i += 2 * blockDim.x) v |= ei32[i];
        if (v) atomicOr(&acc, 1);
        __syncthreads();
        if (threadIdx.x == 0) g_is64 = (acc == 0) ? 1 : 0;
    } else {
        int i = (blockIdx.x - 1) * blockDim.x + threadIdx.x;
        if (i < n) g_deg[i] = 0;
    }
}

// ====== K1: deg+slot ∥ split_src ∥ split_wt1 ∥ split_wt2 ∥ split_wc ==========
__global__ void k1_prep(const void* __restrict__ ei, int E,
                        const float* __restrict__ x,
                        const float* __restrict__ W1, const float* __restrict__ W2,
                        const float* __restrict__ Wc,
                        int n, int bDeg, int bSplit, int bW1, int bW2) {
    int b = blockIdx.x, tid = threadIdx.x;
    if (b < bDeg) {
        int is64 = g_is64;
        int base = (b * 256 + tid) * 4;
        #pragma unroll
        for (int j = 0; j < 4; j++) {
            int i = base + j;
            if (i < E) {
                int d = load_edge(ei, (long long)E + i, is64);
                if ((unsigned)d < (unsigned)NN)
                    g_slot[i] = atomicAdd(&g_deg[d], 1);   // slot = position in row
            }
        }
    } else if (b < bDeg + bSplit) {
        int id = (b - bDeg) * 256 + tid;
        int nf4 = n * F0 / 4;
        if (id < nf4) {
            float4 v = ((const float4*)x)[id];
            __nv_bfloat16 h0, h1, h2, h3, l0, l1, l2, l3;
            split1(v.x, h0, l0); split1(v.y, h1, l1);
            split1(v.z, h2, l2); split1(v.w, h3, l3);
            __nv_bfloat162 hp0; hp0.x = h0; hp0.y = h1;
            __nv_bfloat162 hp1; hp1.x = h2; hp1.y = h3;
            __nv_bfloat162 lp0; lp0.x = l0; lp0.y = l1;
            __nv_bfloat162 lp1; lp1.x = l2; lp1.y = l3;
            ((__nv_bfloat162*)g_Ahi)[id * 2] = hp0;
            ((__nv_bfloat162*)g_Ahi)[id * 2 + 1] = hp1;
            ((__nv_bfloat162*)g_Alo)[id * 2] = lp0;
            ((__nv_bfloat162*)g_Alo)[id * 2 + 1] = lp1;
        }
    } else if (b < bDeg + bSplit + bW1) {
        int i = (b - bDeg - bSplit) * 256 + tid;
        if (i < F0 * FH) {
            int k = i / FH, nidx = i % FH;
            __nv_bfloat16 hi, lo;
            split1(W1[i], hi, lo);
            g_W1thi[nidx * F0 + k] = hi;
            g_W1tlo[nidx * F0 + k] = lo;
        }
    } else if (b < bDeg + bSplit + bW1 + bW2) {
        int i = (b - bDeg - bSplit - bW1) * 256 + tid;
        if (i < FH * FH) {
            int k = i / FH, nidx = i % FH;
            __nv_bfloat16 hi, lo;
            split1(W2[i], hi, lo);
            g_W2thi[nidx * FH + k] = hi;
            g_W2tlo[nidx * FH + k] = lo;
        }
    } else {
        // Wc[K=128][N=40] -> [64 pad][128] K-major hi/lo
        int i = (b - bDeg - bSplit - bW1 - bW2) * 256 + tid;
        if (i < 64 * FH) {
            int nidx = i / FH, k = i % FH;
            float f = (nidx < FC) ? Wc[k * FC + nidx] : 0.f;
            __nv_bfloat16 hi, lo;
            split1(f, hi, lo);
            g_Wcthi[nidx * FH + k] = hi;
            g_Wctlo[nidx * FH + k] = lo;
        }
    }
}

// ============ GEMM device body (mma.sync bf16, cp.async 2-stage) =============
#define SKEW 40
#define TILE_B (128 * SKEW * 2)
#define STAGE_B (4 * TILE_B)
#define GSM_TOTAL (2 * STAGE_B)     // 81920 bytes

__device__ __forceinline__ void gemm_load_stage(
    uint32_t sbase, const __nv_bfloat16* __restrict__ Ah, const __nv_bfloat16* __restrict__ Al,
    const __nv_bfloat16* __restrict__ Bh, const __nv_bfloat16* __restrict__ Bl,
    int m0, int kc, int K, int M)
{
    int tid = threadIdx.x;
    #pragma unroll
    for (int it = 0; it < 2; it++) {
        int id = it * 256 + tid;
        int row = id >> 2, seg = id & 3;
        uint32_t soff = (uint32_t)(row * SKEW + seg * 8) * 2;
        int gr = m0 + row;
        int ok = (gr < M) ? 16 : 0;
        size_t grc = (gr < M) ? (size_t)gr : 0;
        CP_ASYNC16(sbase + soff,               Ah + grc * K + kc + seg * 8, ok);
        CP_ASYNC16(sbase + TILE_B + soff,      Al + grc * K + kc + seg * 8, ok);
        CP_ASYNC16(sbase + 2 * TILE_B + soff,  Bh + (size_t)row * K + kc + seg * 8, 16);
        CP_ASYNC16(sbase + 3 * TILE_B + soff,  Bl + (size_t)row * K + kc + seg * 8, 16);
    }
}

__device__ void mma_gemm_dev(char* smem, int bidx, int layer, int M, int K) {
    uint32_t sb = smem_u32(smem);
    const __nv_bfloat16* Bh = (layer == 1) ? g_W1thi : g_W2thi;
    const __nv_bfloat16* Bl = (layer == 1) ? g_W1tlo : g_W2tlo;

    int tid = threadIdx.x, wid = tid >> 5, lane = tid & 31;
    int m0 = bidx * 128;
    int warp_m = wid & 3, warp_n = wid >> 2;

    float acc[2][8][4] = {};

    int nch = K >> 5;
    gemm_load_stage(sb, g_Ahi, g_Alo, Bh, Bl, m0, 0, K, M);
    CP_COMMIT;

    for (int c = 0; c < nch; c++) {
        if (c + 1 < nch) {
            gemm_load_stage(sb + ((c + 1) & 1) * STAGE_B, g_Ahi, g_Alo, Bh, Bl,
                            m0, (c + 1) << 5, K, M);
            CP_COMMIT;
            CP_WAIT(1);
        } else {
            CP_WAIT(0);
        }
        __syncthreads();

        uint32_t stg = sb + (c & 1) * STAGE_B;
        uint32_t aAhi = stg, aAlo = stg + TILE_B;
        uint32_t aBhi = stg + 2 * TILE_B, aBlo = stg + 3 * TILE_B;

        #pragma unroll
        for (int kk = 0; kk < 32; kk += 16) {
            uint32_t ah[2][4], al[2][4];
            #pragma unroll
            for (int mi = 0; mi < 2; mi++) {
                int row = warp_m * 32 + mi * 16 + (lane & 15);
                int col = kk + (lane >> 4) * 8;
                uint32_t off = (uint32_t)(row * SKEW + col) * 2;
                LDSM_X4(ah[mi][0], ah[mi][1], ah[mi][2], ah[mi][3], aAhi + off);
                LDSM_X4(al[mi][0], al[mi][1], al[mi][2], al[mi][3], aAlo + off);
            }
            uint32_t b[8][2];
            int g = lane >> 3;
            #pragma unroll
            for (int p = 0; p < 4; p++) {
                int nrow = warp_n * 64 + p * 16 + (g >> 1) * 8 + (lane & 7);
                int col = kk + (g & 1) * 8;
                uint32_t off = (uint32_t)(nrow * SKEW + col) * 2;
                uint32_t r0, r1, r2, r3;
                LDSM_X4(r0, r1, r2, r3, aBhi + off);
                b[p * 2][0] = r0; b[p * 2][1] = r1;
                b[p * 2 + 1][0] = r2; b[p * 2 + 1][1] = r3;
            }
            #pragma unroll
            for (int mi = 0; mi < 2; mi++)
                #pragma unroll
                for (int ni = 0; ni < 8; ni++) {
                    MMA16816(acc[mi][ni], ah[mi], b[ni]);
                    MMA16816(acc[mi][ni], al[mi], b[ni]);
                }
            #pragma unroll
            for (int p = 0; p < 4; p++) {
                int nrow = warp_n * 64 + p * 16 + (g >> 1) * 8 + (lane & 7);
                int col = kk + (g & 1) * 8;
                uint32_t off = (uint32_t)(nrow * SKEW + col) * 2;
                uint32_t r0, r1, r2, r3;
                LDSM_X4(r0, r1, r2, r3, aBlo + off);
                b[p * 2][0] = r0; b[p * 2][1] = r1;
                b[p * 2 + 1][0] = r2; b[p * 2 + 1][1] = r3;
            }
            #pragma unroll
            for (int mi = 0; mi < 2; mi++)
                #pragma unroll
                for (int ni = 0; ni < 8; ni++)
                    MMA16816(acc[mi][ni], ah[mi], b[ni]);
        }
        __syncthreads();
    }

    int gid = lane >> 2, tig = lane & 3;
    #pragma unroll
    for (int mi = 0; mi < 2; mi++) {
        #pragma unroll
        for (int ni = 0; ni < 8; ni++) {
            int col = warp_n * 64 + ni * 8 + tig * 2;
            int r0 = m0 + warp_m * 32 + mi * 16 + gid;
            if (r0 < M)
                *(float2*)(g_h + (size_t)r0 * 128 + col) =
                    make_float2(acc[mi][ni][0], acc[mi][ni][1]);
            int r1 = r0 + 8;
            if (r1 < M)
                *(float2*)(g_h + (size_t)r1 * 128 + col) =
                    make_float2(acc[mi][ni][2], acc[mi][ni][3]);
        }
    }
}

// ============ K2: GEMM-1 ∥ exclusive scan (1 block) ∥ dinv ====================
__global__ void __launch_bounds__(256, 2) k2_gemm1_scan_dinv(int M, int n, int gemmB) {
    extern __shared__ char smem[];
    int b = blockIdx.x;
    if (b < gemmB) {
        mma_gemm_dev(smem, b, 1, M, F0);
    } else if (b == gemmB) {
        __shared__ int sh[256];
        int tid = threadIdx.x;
        int chunk = (n + 255) >> 8;
        int start = tid * chunk, end = min(start + chunk, n);
        int sum = 0;
        for (int i = start; i < end; i++) sum += g_deg[i];
        sh[tid] = sum;
        __syncthreads();
        for (int off = 1; off < 256; off <<= 1) {
            int v = 0;
            if (tid >= off) v = sh[tid - off];
            __syncthreads();
            sh[tid] += v;
            __syncthreads();
        }
        int run = sh[tid] - sum;
        for (int i = start; i < end; i++) { g_rowptr[i] = run; run += g_deg[i]; }
        if (end == n) g_rowptr[n] = run;
    } else {
        int i = (b - gemmB - 1) * 256 + threadIdx.x;
        if (i < n) g_dinv[i] = rsqrtf((float)g_deg[i] + 1.0f);
    }
}

__global__ void __launch_bounds__(256, 2) mma_gemm2(int M) {
    extern __shared__ char smem[];
    mma_gemm_dev(smem, blockIdx.x, 2, M, FH);
}

// ============ K3: CSR scatter — atomic-free (uses precomputed slots) =========
__global__ void k3_scatter(const void* __restrict__ ei, int E) {
    int is64 = g_is64;
    int base = (blockIdx.x * 256 + threadIdx.x) * 4;
    #pragma unroll
    for (int j = 0; j < 4; j++) {
        int i = base + j;
        if (i >= E) break;
        int s = load_edge(ei, i, is64);
        int d = load_edge(ei, (long long)E + i, is64);
        if ((unsigned)s >= (unsigned)NN || (unsigned)d >= (unsigned)NN) continue;
        int pos = g_rowptr[d] + g_slot[i];
        g_col[pos] = s;
        g_w[pos]   = g_dinv[s] * g_dinv[d];
    }
}

// ---------------- aggregation: warp per node, 2-way ILP, bf16 hi/lo out ------
__global__ void agg_kernel(const float* __restrict__ bias, int n) {
    int warp = (blockIdx.x * blockDim.x + threadIdx.x) >> 5;
    if (warp >= n) return;
    int lane = threadIdx.x & 31;
    int beg = g_rowptr[warp], end = g_rowptr[warp + 1];
    const float4* hv = (const float4*)g_h;

    float4 acc0 = make_float4(0.f, 0.f, 0.f, 0.f);
    float4 acc1 = make_float4(0.f, 0.f, 0.f, 0.f);
    int e = beg;
    for (; e + 2 <= end; e += 2) {
        int s0 = g_col[e], s1 = g_col[e + 1];
        float w0 = g_w[e], w1 = g_w[e + 1];
        float4 v0 = hv[(size_t)s0 * 32 + lane];
        float4 v1 = hv[(size_t)s1 * 32 + lane];
        acc0.x += w0 * v0.x; acc0.y += w0 * v0.y;
        acc0.z += w0 * v0.z; acc0.w += w0 * v0.w;
        acc1.x += w1 * v1.x; acc1.y += w1 * v1.y;
        acc1.z += w1 * v1.z; acc1.w += w1 * v1.w;
    }
    if (e < end) {
        int s0 = g_col[e];
        float w0 = g_w[e];
        float4 v0 = hv[(size_t)s0 * 32 + lane];
        acc0.x += w0 * v0.x; acc0.y += w0 * v0.y;
        acc0.z += w0 * v0.z; acc0.w += w0 * v0.w;
    }
    acc0.x += acc1.x; acc0.y += acc1.y; acc0.z += acc1.z; acc0.w += acc1.w;

    float di = g_dinv[warp], di2 = di * di;
    float4 hs = hv[(size_t)warp * 32 + lane];
    float4 bb = ((const float4*)bias)[lane];
    float4 r;
    r.x = fmaxf(acc0.x + di2 * hs.x + bb.x, 0.f);
    r.y = fmaxf(acc0.y + di2 * hs.y + bb.y, 0.f);
    r.z = fmaxf(acc0.z + di2 * hs.z + bb.z, 0.f);
    r.w = fmaxf(acc0.w + di2 * hs.w + bb.w, 0.f);

    __nv_bfloat16 h0, h1, h2, h3, l0, l1, l2, l3;
    split1(r.x, h0, l0); split1(r.y, h1, l1);
    split1(r.z, h2, l2); split1(r.w, h3, l3);
    __nv_bfloat162 hp0; hp0.x = h0; hp0.y = h1;
    __nv_bfloat162 hp1; hp1.x = h2; hp1.y = h3;
    __nv_bfloat162 lp0; lp0.x = l0; lp0.y = l1;
    __nv_bfloat162 lp1; lp1.x = l2; lp1.y = l3;
    size_t idx2 = (size_t)warp * 64 + lane * 2;   // row stride 128 bf16
    ((__nv_bfloat162*)g_Ahi)[idx2] = hp0;
    ((__nv_bfloat162*)g_Ahi)[idx2 + 1] = hp1;
    ((__nv_bfloat162*)g_Alo)[idx2] = lp0;
    ((__nv_bfloat162*)g_Alo)[idx2 + 1] = lp1;
}

// ============ classifier: bf16 HMMA, BM=128 BN=64(40) K=128, 3-term ==========
#define CTILE_A (128 * SKEW * 2)    // 10240
#define CTILE_Bc (64 * SKEW * 2)    // 5120
#define CSTAGE (2 * CTILE_A + 2 * CTILE_Bc)   // 30720
#define CSM_TOTAL (2 * CSTAGE)                // 61440

__device__ __forceinline__ void clf_load_stage(uint32_t sbase, int m0, int kc, int M) {
    int tid = threadIdx.x;
    // A hi/lo: 512 segs each
    #pragma unroll
    for (int it = 0; it < 2; it++) {
        int id = it * 256 + tid;
        int row = id >> 2, seg = id & 3;
        uint32_t soff = (uint32_t)(row * SKEW + seg * 8) * 2;
        int gr = m0 + row;
        int ok = (gr < M) ? 16 : 0;
        size_t grc = (gr < M) ? (size_t)gr : 0;
        CP_ASYNC16(sbase + soff,            g_Ahi + grc * FH + kc + seg * 8, ok);
        CP_ASYNC16(sbase + CTILE_A + soff,  g_Alo + grc * FH + kc + seg * 8, ok);
    }
    // B hi/lo: 256 segs each
    {
        int row = tid >> 2, seg = tid & 3;   // 64 rows x 4 segs
        uint32_t soff = (uint32_t)(row * SKEW + seg * 8) * 2;
        CP_ASYNC16(sbase + 2 * CTILE_A + soff,            g_Wcthi + (size_t)row * FH + kc + seg * 8, 16);
        CP_ASYNC16(sbase + 2 * CTILE_A + CTILE_Bc + soff, g_Wctlo + (size_t)row * FH + kc + seg * 8, 16);
    }
}

__global__ void __launch_bounds__(256, 2) mma_clf(const float* __restrict__ bias,
                                                  float* __restrict__ out, int M) {
    extern __shared__ char smem[];
    uint32_t sb = smem_u32(smem);
    int tid = threadIdx.x, wid = tid >> 5, lane = tid & 31;
    int m0 = blockIdx.x * 128;
    int warp_m = wid & 3, warp_n = wid >> 2;   // warp tile 32x32

    float acc[2][4][4] = {};

    const int nch = FH >> 5;   // 4
    clf_load_stage(sb, m0, 0, M);
    CP_COMMIT;

    for (int c = 0; c < nch; c++) {
        if (c + 1 < nch) {
            clf_load_stage(sb + ((c + 1) & 1) * CSTAGE, m0, (c + 1) << 5, M);
            CP_COMMIT;
            CP_WAIT(1);
        } else {
            CP_WAIT(0);
        }
        __syncthreads();

        uint32_t stg = sb + (c & 1) * CSTAGE;
        uint32_t aAhi = stg, aAlo = stg + CTILE_A;
        uint32_t aBhi = stg + 2 * CTILE_A, aBlo = aBhi + CTILE_Bc;

        #pragma unroll
        for (int kk = 0; kk < 32; kk += 16) {
            uint32_t ah[2][4], al[2][4];
            #pragma unroll
            for (int mi = 0; mi < 2; mi++) {
                int row = warp_m * 32 + mi * 16 + (lane & 15);
                int col = kk + (lane >> 4) * 8;
                uint32_t off = (uint32_t)(row * SKEW + col) * 2;
                LDSM_X4(ah[mi][0], ah[mi][1], ah[mi][2], ah[mi][3], aAhi + off);
                LDSM_X4(al[mi][0], al[mi][1], al[mi][2], al[mi][3], aAlo + off);
            }
            uint32_t b[4][2];
            int g = lane >> 3;
            #pragma unroll
            for (int p = 0; p < 2; p++) {
                int nrow = warp_n * 32 + p * 16 + (g >> 1) * 8 + (lane & 7);
                int col = kk + (g & 1) * 8;
                uint32_t off = (uint32_t)(nrow * SKEW + col) * 2;
                uint32_t r0, r1, r2, r3;
                LDSM_X4(r0, r1, r2, r3, aBhi + off);
                b[p * 2][0] = r0; b[p * 2][1] = r1;
                b[p * 2 + 1][0] = r2; b[p * 2 + 1][1] = r3;
            }
            #pragma unroll
            for (int mi = 0; mi < 2; mi++)
                #pragma unroll
                for (int ni = 0; ni < 4; ni++) {
                    MMA16816(acc[mi][ni], ah[mi], b[ni]);
                    MMA16816(acc[mi][ni], al[mi], b[ni]);
                }
            #pragma unroll
            for (int p = 0; p < 2; p++) {
                int nrow = warp_n * 32 + p * 16 + (g >> 1) * 8 + (lane & 7);
                int col = kk + (g & 1) * 8;
                uint32_t off = (uint32_t)(nrow * SKEW + col) * 2;
                uint32_t r0, r1, r2, r3;
                LDSM_X4(r0, r1, r2, r3, aBlo + off);
                b[p * 2][0] = r0; b[p * 2][1] = r1;
                b[p * 2 + 1][0] = r2; b[p * 2 + 1][1] = r3;
            }
            #pragma unroll
            for (int mi = 0; mi < 2; mi++)
                #pragma unroll
                for (int ni = 0; ni < 4; ni++)
                    MMA16816(acc[mi][ni], ah[mi], b[ni]);
        }
        __syncthreads();
    }

    // epilogue: out[M][40], add bias, only cols < 40
    int gid = lane >> 2, tig = lane & 3;
    #pragma unroll
    for (int mi = 0; mi < 2; mi++) {
        #pragma unroll
        for (int ni = 0; ni < 4; ni++) {
            int col = warp_n * 32 + ni * 8 + tig * 2;
            if (col >= FC) continue;
            float b0 = bias[col], b1 = bias[col + 1];
            int r0 = m0 + warp_m * 32 + mi * 16 + gid;
            if (r0 < M)
                *(float2*)(out + (size_t)r0 * FC + col) =
                    make_float2(acc[mi][ni][0] + b0, acc[mi][ni][1] + b1);
            int r1 = r0 + 8;
            if (r1 < M)
                *(float2*)(out + (size_t)r1 * FC + col) =
                    make_float2(acc[mi][ni][2] + b0, acc[mi][ni][3] + b1);
        }
    }
}

// ---------------- launch ----------------
extern "C" void kernel_launch(void* const* d_in, const int* in_sizes, int n_in,
                              void* d_out, int out_size) {
    const float* x  = (const float*)d_in[0];
    const void*  ei = d_in[1];
    const float* W1 = (const float*)d_in[2];
    const float* b1 = (const float*)d_in[3];
    const float* W2 = (const float*)d_in[4];
    const float* b2 = (const float*)d_in[5];
    const float* Wc = (const float*)d_in[6];
    const float* bc = (const float*)d_in[7];
    float*       out = (float*)d_out;

    const int n = in_sizes[0] / F0;   // 100000
    const int E = in_sizes[1] / 2;    // 1600000

    cudaFuncSetAttribute(k2_gemm1_scan_dinv, cudaFuncAttributeMaxDynamicSharedMemorySize, GSM_TOTAL);
    cudaFuncSetAttribute(mma_gemm2, cudaFuncAttributeMaxDynamicSharedMemorySize, GSM_TOTAL);
    cudaFuncSetAttribute(mma_clf, cudaFuncAttributeMaxDynamicSharedMemorySize, CSM_TOTAL);

    int zB     = (n + 255) / 256;
    int bDeg   = (E + 1023) / 1024;
    int bSplit = (n * F0 / 4 + 255) / 256;
    int bW1    = (F0 * FH + 255) / 256;
    int bW2    = (FH * FH + 255) / 256;
    int bWc    = (64 * FH + 255) / 256;
    int gemmB  = (n + 127) / 128;
    int dinvB  = (n + 255) / 256;

    k0_detect_zero<<<1 + zB, 256>>>((const int*)ei, 2 * E, n);
    k1_prep<<<bDeg + bSplit + bW1 + bW2 + bWc, 256>>>(ei, E, x, W1, W2, Wc,
                                                      n, bDeg, bSplit, bW1, bW2);
    k2_gemm1_scan_dinv<<<gemmB + 1 + dinvB, 256, GSM_TOTAL>>>(n, n, gemmB);
    k3_scatter<<<(E + 1023) / 1024, 256>>>(ei, E);
    agg_kernel<<<(n + 7) / 8, 256>>>(b1, n);
    mma_gemm2<<<gemmB, 256, GSM_TOTAL>>>(n);
    agg_kernel<<<(n + 7) / 8, 256>>>(b2, n);
    mma_clf<<<gemmB, 256, CSM_TOTAL>>>(bc, out, n);
}

// round 11
// speedup vs baseline: 1.4944x; 1.0538x over previous
#include <cuda_runtime.h>
#include <cuda_bf16.h>
#include <cstdint>

#define NN 100000
#define EE 1600000
#define F0 256
#define FH 128
#define FC 40

// ---------------- static device scratch ----------------
__device__ float g_h[(size_t)NN * FH];
__device__ int   g_deg[NN];
__device__ float g_dinv[NN];
__device__ int   g_rowptr[NN + 1];
__device__ int   g_col[EE];
__device__ int   g_slot[EE];
__device__ float g_w[EE];
__device__ int   g_is64;
__device__ __nv_bfloat16 g_Ahi[(size_t)NN * FH];   // layer-2 input (from agg1)
__device__ __nv_bfloat16 g_Alo[(size_t)NN * FH];
__device__ __nv_bfloat16 g_W1thi[FH * F0], g_W1tlo[FH * F0];   // [128][256] K-major
__device__ __nv_bfloat16 g_W2thi[FH * FH], g_W2tlo[FH * FH];   // [128][128] K-major
__device__ __nv_bfloat16 g_Wcthi[64 * FH], g_Wctlo[64 * FH];   // [64(pad40)][128] K-major

// ---------------- helpers ----------------
__device__ __forceinline__ uint32_t smem_u32(const void* p) {
    uint32_t a;
    asm("{ .reg .u64 t; cvta.to.shared.u64 t, %1; cvt.u32.u64 %0, t; }" : "=r"(a) : "l"(p));
    return a;
}
#define LDSM_X4(r0, r1, r2, r3, addr) \
    asm volatile("ldmatrix.sync.aligned.m8n8.x4.shared.b16 {%0,%1,%2,%3}, [%4];" \
                 : "=r"(r0), "=r"(r1), "=r"(r2), "=r"(r3) : "r"(addr))
#define MMA16816(d, a, b) \
    asm volatile("mma.sync.aligned.m16n8k16.row.col.f32.bf16.bf16.f32 " \
                 "{%0,%1,%2,%3}, {%4,%5,%6,%7}, {%8,%9}, {%0,%1,%2,%3};" \
                 : "+f"((d)[0]), "+f"((d)[1]), "+f"((d)[2]), "+f"((d)[3]) \
                 : "r"((a)[0]), "r"((a)[1]), "r"((a)[2]), "r"((a)[3]), \
                   "r"((b)[0]), "r"((b)[1]))
#define CP_ASYNC16(dst, src, sz) \
    asm volatile("cp.async.cg.shared.global [%0], [%1], 16, %2;" \
                 :: "r"(dst), "l"(src), "r"(sz) : "memory")
#define CP_COMMIT asm volatile("cp.async.commit_group;" ::: "memory")
#define CP_WAIT(n) asm volatile("cp.async.wait_group %0;" :: "n"(n) : "memory")

__device__ __forceinline__ int load_edge(const void* ei, long long idx, int is64) {
    if (is64) return (int)((const long long*)ei)[idx];
    return ((const int*)ei)[idx];
}
__device__ __forceinline__ void split1(float f, __nv_bfloat16& hi, __nv_bfloat16& lo) {
    hi = __float2bfloat16(f);
    lo = __float2bfloat16(f - __bfloat162float(hi));
}

#define SKEW 40
#define TILE_B (128 * SKEW * 2)     // 10240 bytes
#define STAGE_B (4 * TILE_B)
#define GSM_TOTAL (2 * STAGE_B)     // 81920

// ================= K0: detect dtype + zero deg ===============================
__global__ void k0_detect_zero(const int* __restrict__ ei32, int total_words, int n) {
    if (blockIdx.x == 0) {
        __shared__ int acc;
        if (threadIdx.x == 0) acc = 0;
        __syncthreads();
        int v = 0;
        int lim = min(total_words, 8192);
        for (int i = 1 + 2 * threadIdx.x; i < lim; i += 2 * blockDim.x) v |= ei32[i];
        if (v) atomicOr(&acc, 1);
        __syncthreads();
        if (threadIdx.x == 0) g_is64 = (acc == 0) ? 1 : 0;
    } else {
        int i = (blockIdx.x - 1) * blockDim.x + threadIdx.x;
        if (i < n) g_deg[i] = 0;
    }
}

// ====== K1: deg+slot ∥ split_wt1 ∥ split_wt2 ∥ split_wc ======================
__global__ void k1_prep(const void* __restrict__ ei, int E,
                        const float* __restrict__ W1, const float* __restrict__ W2,
                        const float* __restrict__ Wc,
                        int bDeg, int bW1, int bW2) {
    int b = blockIdx.x, tid = threadIdx.x;
    if (b < bDeg) {
        int is64 = g_is64;
        int base = (b * 256 + tid) * 4;
        #pragma unroll
        for (int j = 0; j < 4; j++) {
            int i = base + j;
            if (i < E) {
                int d = load_edge(ei, (long long)E + i, is64);
                if ((unsigned)d < (unsigned)NN)
                    g_slot[i] = atomicAdd(&g_deg[d], 1);
            }
        }
    } else if (b < bDeg + bW1) {
        int i = (b - bDeg) * 256 + tid;
        if (i < F0 * FH) {
            int k = i / FH, nidx = i % FH;
            __nv_bfloat16 hi, lo;
            split1(W1[i], hi, lo);
            g_W1thi[nidx * F0 + k] = hi;
            g_W1tlo[nidx * F0 + k] = lo;
        }
    } else if (b < bDeg + bW1 + bW2) {
        int i = (b - bDeg - bW1) * 256 + tid;
        if (i < FH * FH) {
            int k = i / FH, nidx = i % FH;
            __nv_bfloat16 hi, lo;
            split1(W2[i], hi, lo);
            g_W2thi[nidx * FH + k] = hi;
            g_W2tlo[nidx * FH + k] = lo;
        }
    } else {
        int i = (b - bDeg - bW1 - bW2) * 256 + tid;
        if (i < 64 * FH) {
            int nidx = i / FH, k = i % FH;
            float f = (nidx < FC) ? Wc[k * FC + nidx] : 0.f;
            __nv_bfloat16 hi, lo;
            split1(f, hi, lo);
            g_Wcthi[nidx * FH + k] = hi;
            g_Wctlo[nidx * FH + k] = lo;
        }
    }
}

// ====== K1b: exclusive scan (block 0) ∥ dinv =================================
__global__ void k1b_scan_dinv(int n) {
    if (blockIdx.x == 0) {
        __shared__ int sh[256];
        int tid = threadIdx.x;
        int chunk = (n + 255) >> 8;
        int start = tid * chunk, end = min(start + chunk, n);
        int sum = 0;
        for (int i = start; i < end; i++) sum += g_deg[i];
        sh[tid] = sum;
        __syncthreads();
        for (int off = 1; off < 256; off <<= 1) {
            int v = 0;
            if (tid >= off) v = sh[tid - off];
            __syncthreads();
            sh[tid] += v;
            __syncthreads();
        }
        int run = sh[tid] - sum;
        for (int i = start; i < end; i++) { g_rowptr[i] = run; run += g_deg[i]; }
        if (end == n) g_rowptr[n] = run;
    } else {
        int i = (blockIdx.x - 1) * 256 + threadIdx.x;
        if (i < n) g_dinv[i] = rsqrtf((float)g_deg[i] + 1.0f);
    }
}

// ============ shared MMA compute for one 32-wide K chunk =====================
__device__ __forceinline__ void compute_chunk(
    uint32_t aAhi, uint32_t aAlo, uint32_t aBhi, uint32_t aBlo,
    int warp_m, int warp_n, int lane, float acc[2][8][4])
{
    #pragma unroll
    for (int kk = 0; kk < 32; kk += 16) {
        uint32_t ah[2][4], al[2][4];
        #pragma unroll
        for (int mi = 0; mi < 2; mi++) {
            int row = warp_m * 32 + mi * 16 + (lane & 15);
            int col = kk + (lane >> 4) * 8;
            uint32_t off = (uint32_t)(row * SKEW + col) * 2;
            LDSM_X4(ah[mi][0], ah[mi][1], ah[mi][2], ah[mi][3], aAhi + off);
            LDSM_X4(al[mi][0], al[mi][1], al[mi][2], al[mi][3], aAlo + off);
        }
        uint32_t b[8][2];
        int g = lane >> 3;
        #pragma unroll
        for (int p = 0; p < 4; p++) {
            int nrow = warp_n * 64 + p * 16 + (g >> 1) * 8 + (lane & 7);
            int col = kk + (g & 1) * 8;
            uint32_t off = (uint32_t)(nrow * SKEW + col) * 2;
            uint32_t r0, r1, r2, r3;
            LDSM_X4(r0, r1, r2, r3, aBhi + off);
            b[p * 2][0] = r0; b[p * 2][1] = r1;
            b[p * 2 + 1][0] = r2; b[p * 2 + 1][1] = r3;
        }
        #pragma unroll
        for (int mi = 0; mi < 2; mi++)
            #pragma unroll
            for (int ni = 0; ni < 8; ni++) {
                MMA16816(acc[mi][ni], ah[mi], b[ni]);
                MMA16816(acc[mi][ni], al[mi], b[ni]);
            }
        #pragma unroll
        for (int p = 0; p < 4; p++) {
            int nrow = warp_n * 64 + p * 16 + (g >> 1) * 8 + (lane & 7);
            int col = kk + (g & 1) * 8;
            uint32_t off = (uint32_t)(nrow * SKEW + col) * 2;
            uint32_t r0, r1, r2, r3;
            LDSM_X4(r0, r1, r2, r3, aBlo + off);
            b[p * 2][0] = r0; b[p * 2][1] = r1;
            b[p * 2 + 1][0] = r2; b[p * 2 + 1][1] = r3;
        }
        #pragma unroll
        for (int mi = 0; mi < 2; mi++)
            #pragma unroll
            for (int ni = 0; ni < 8; ni++)
                MMA16816(acc[mi][ni], ah[mi], b[ni]);
    }
}

__device__ __forceinline__ void gemm_epilogue(float acc[2][8][4], int m0,
                                              int warp_m, int warp_n, int lane, int M) {
    int gid = lane >> 2, tig = lane & 3;
    #pragma unroll
    for (int mi = 0; mi < 2; mi++) {
        #pragma unroll
        for (int ni = 0; ni < 8; ni++) {
            int col = warp_n * 64 + ni * 8 + tig * 2;
            int r0 = m0 + warp_m * 32 + mi * 16 + gid;
            if (r0 < M)
                *(float2*)(g_h + (size_t)r0 * 128 + col) =
                    make_float2(acc[mi][ni][0], acc[mi][ni][1]);
            int r1 = r0 + 8;
            if (r1 < M)
                *(float2*)(g_h + (size_t)r1 * 128 + col) =
                    make_float2(acc[mi][ni][2], acc[mi][ni][3]);
        }
    }
}

// ============ GEMM-1: reads x fp32 directly, splits on the fly ===============
// smem: A hi/lo single buffer [0, 2*TILE_B); B double-buffered [2*TILE_B, ...)
// RACE FIX vs R10: __syncthreads() at TOP of loop, BEFORE issuing the B
// prefetch (which writes a buffer of the same parity the previous-previous
// compute read) and before the A STS.
__device__ void mma_gemm1_dev(char* smem, int bidx, const float* __restrict__ x, int M) {
    uint32_t sb = smem_u32(smem);
    int tid = threadIdx.x, wid = tid >> 5, lane = tid & 31;
    int m0 = bidx * 128;
    int warp_m = wid & 3, warp_n = wid >> 2;
    const int K = F0, nch = K >> 5;   // 8

    float acc[2][8][4] = {};
    float4 f[4];

    #define L1_LOADB(c) do { \
        uint32_t base = sb + 2 * TILE_B + ((c) & 1) * (2 * TILE_B); \
        _Pragma("unroll") \
        for (int it = 0; it < 2; it++) { \
            int id = it * 256 + tid; \
            int row = id >> 2, seg = id & 3; \
            uint32_t soff = (uint32_t)(row * SKEW + seg * 8) * 2; \
            CP_ASYNC16(base + soff,          g_W1thi + (size_t)row * K + ((c) << 5) + seg * 8, 16); \
            CP_ASYNC16(base + TILE_B + soff, g_W1tlo + (size_t)row * K + ((c) << 5) + seg * 8, 16); \
        } \
        CP_COMMIT; \
    } while (0)
    #define L1_LOADA(c) do { \
        _Pragma("unroll") \
        for (int it = 0; it < 4; it++) { \
            int id = it * 256 + tid; \
            int row = id >> 3, seg = id & 7; \
            int gr = m0 + row; \
            f[it] = (gr < M) ? *(const float4*)(x + (size_t)gr * K + ((c) << 5) + seg * 4) \
                             : make_float4(0.f, 0.f, 0.f, 0.f); \
        } \
    } while (0)

    L1_LOADB(0);
    L1_LOADA(0);

    for (int c = 0; c < nch; c++) {
        __syncthreads();   // ALL reads of A smem & B[(c+1)&1] from prior iters done
        if (c + 1 < nch) L1_LOADB(c + 1);
        // convert + STS A chunk c (f registers dead after)
        #pragma unroll
        for (int it = 0; it < 4; it++) {
            int id = it * 256 + tid;
            int row = id >> 3, seg = id & 7;
            __nv_bfloat16 h0, h1, h2, h3, l0, l1, l2, l3;
            split1(f[it].x, h0, l0); split1(f[it].y, h1, l1);
            split1(f[it].z, h2, l2); split1(f[it].w, h3, l3);
            __nv_bfloat162 hp0; hp0.x = h0; hp0.y = h1;
            __nv_bfloat162 hp1; hp1.x = h2; hp1.y = h3;
            __nv_bfloat162 lp0; lp0.x = l0; lp0.y = l1;
            __nv_bfloat162 lp1; lp1.x = l2; lp1.y = l3;
            uint32_t soff = (uint32_t)(row * SKEW + seg * 4) * 2;
            *(uint2*)(smem + soff) = make_uint2(*(uint32_t*)&hp0, *(uint32_t*)&hp1);
            *(uint2*)(smem + TILE_B + soff) = make_uint2(*(uint32_t*)&lp0, *(uint32_t*)&lp1);
        }
        if (c + 1 < nch) { L1_LOADA(c + 1); CP_WAIT(1); }
        else             { CP_WAIT(0); }
        __syncthreads();

        uint32_t aBhi = sb + 2 * TILE_B + (c & 1) * (2 * TILE_B);
        compute_chunk(sb, sb + TILE_B, aBhi, aBhi + TILE_B, warp_m, warp_n, lane, acc);
    }
    gemm_epilogue(acc, m0, warp_m, warp_n, lane, M);
    #undef L1_LOADB
    #undef L1_LOADA
}

// ============ GEMM-2: bf16 A from g_Ahi/g_Alo (cp.async 2-stage) =============
__device__ __forceinline__ void gemm2_load_stage(uint32_t sbase, int m0, int kc, int M) {
    int tid = threadIdx.x;
    #pragma unroll
    for (int it = 0; it < 2; it++) {
        int id = it * 256 + tid;
        int row = id >> 2, seg = id & 3;
        uint32_t soff = (uint32_t)(row * SKEW + seg * 8) * 2;
        int gr = m0 + row;
        int ok = (gr < M) ? 16 : 0;
        size_t grc = (gr < M) ? (size_t)gr : 0;
        CP_ASYNC16(sbase + soff,              g_Ahi + grc * FH + kc + seg * 8, ok);
        CP_ASYNC16(sbase + TILE_B + soff,     g_Alo + grc * FH + kc + seg * 8, ok);
        CP_ASYNC16(sbase + 2 * TILE_B + soff, g_W2thi + (size_t)row * FH + kc + seg * 8, 16);
        CP_ASYNC16(sbase + 3 * TILE_B + soff, g_W2tlo + (size_t)row * FH + kc + seg * 8, 16);
    }
}

__global__ void __launch_bounds__(256, 2) mma_gemm2(int M) {
    extern __shared__ char smem[];
    uint32_t sb = smem_u32(smem);
    int tid = threadIdx.x, wid = tid >> 5, lane = tid & 31;
    int m0 = blockIdx.x * 128;
    int warp_m = wid & 3, warp_n = wid >> 2;

    float acc[2][8][4] = {};
    const int nch = FH >> 5;   // 4

    gemm2_load_stage(sb, m0, 0, M);
    CP_COMMIT;
    for (int c = 0; c < nch; c++) {
        if (c + 1 < nch) {
            gemm2_load_stage(sb + ((c + 1) & 1) * STAGE_B, m0, (c + 1) << 5, M);
            CP_COMMIT;
            CP_WAIT(1);
        } else {
            CP_WAIT(0);
        }
        __syncthreads();
        uint32_t stg = sb + (c & 1) * STAGE_B;
        compute_chunk(stg, stg + TILE_B, stg + 2 * TILE_B, stg + 3 * TILE_B,
                      warp_m, warp_n, lane, acc);
        __syncthreads();
    }
    gemm_epilogue(acc, m0, warp_m, warp_n, lane, M);
}

// ============ K2: GEMM-1 ∥ scatter (scatter hidden under gemm) ===============
__global__ void __launch_bounds__(256, 2) k2_gemm1_scatter(
    const float* __restrict__ x, const void* __restrict__ ei, int M, int E, int gemmB) {
    extern __shared__ char smem[];
    if (blockIdx.x < gemmB) {
        mma_gemm1_dev(smem, blockIdx.x, x, M);
    } else {
        int is64 = g_is64;
        int base = ((blockIdx.x - gemmB) * 256 + threadIdx.x) * 8;
        #pragma unroll
        for (int j = 0; j < 8; j++) {
            int i = base + j;
            if (i >= E) break;
            int s = load_edge(ei, i, is64);
            int d = load_edge(ei, (long long)E + i, is64);
            if ((unsigned)s >= (unsigned)NN || (unsigned)d >= (unsigned)NN) continue;
            int pos = g_rowptr[d] + g_slot[i];
            g_col[pos] = s;
            g_w[pos]   = g_dinv[s] * g_dinv[d];
        }
    }
}

// ---------------- aggregation: warp per node, 2-way ILP, bf16 hi/lo out ------
__global__ void agg_kernel(const float* __restrict__ bias, int n) {
    int warp = (blockIdx.x * blockDim.x + threadIdx.x) >> 5;
    if (warp >= n) return;
    int lane = threadIdx.x & 31;
    int beg = g_rowptr[warp], end = g_rowptr[warp + 1];
    const float4* hv = (const float4*)g_h;

    float4 acc0 = make_float4(0.f, 0.f, 0.f, 0.f);
    float4 acc1 = make_float4(0.f, 0.f, 0.f, 0.f);
    int e = beg;
    for (; e + 2 <= end; e += 2) {
        int s0 = g_col[e], s1 = g_col[e + 1];
        float w0 = g_w[e], w1 = g_w[e + 1];
        float4 v0 = hv[(size_t)s0 * 32 + lane];
        float4 v1 = hv[(size_t)s1 * 32 + lane];
        acc0.x += w0 * v0.x; acc0.y += w0 * v0.y;
        acc0.z += w0 * v0.z; acc0.w += w0 * v0.w;
        acc1.x += w1 * v1.x; acc1.y += w1 * v1.y;
        acc1.z += w1 * v1.z; acc1.w += w1 * v1.w;
    }
    if (e < end) {
        int s0 = g_col[e];
        float w0 = g_w[e];
        float4 v0 = hv[(size_t)s0 * 32 + lane];
        acc0.x += w0 * v0.x; acc0.y += w0 * v0.y;
        acc0.z += w0 * v0.z; acc0.w += w0 * v0.w;
    }
    acc0.x += acc1.x; acc0.y += acc1.y; acc0.z += acc1.z; acc0.w += acc1.w;

    float di = g_dinv[warp], di2 = di * di;
    float4 hs = hv[(size_t)warp * 32 + lane];
    float4 bb = ((const float4*)bias)[lane];
    float4 r;
    r.x = fmaxf(acc0.x + di2 * hs.x + bb.x, 0.f);
    r.y = fmaxf(acc0.y + di2 * hs.y + bb.y, 0.f);
    r.z = fmaxf(acc0.z + di2 * hs.z + bb.z, 0.f);
    r.w = fmaxf(acc0.w + di2 * hs.w + bb.w, 0.f);

    __nv_bfloat16 h0, h1, h2, h3, l0, l1, l2, l3;
    split1(r.x, h0, l0); split1(r.y, h1, l1);
    split1(r.z, h2, l2); split1(r.w, h3, l3);
    __nv_bfloat162 hp0; hp0.x = h0; hp0.y = h1;
    __nv_bfloat162 hp1; hp1.x = h2; hp1.y = h3;
    __nv_bfloat162 lp0; lp0.x = l0; lp0.y = l1;
    __nv_bfloat162 lp1; lp1.x = l2; lp1.y = l3;
    size_t idx2 = (size_t)warp * 64 + lane * 2;
    ((__nv_bfloat162*)g_Ahi)[idx2] = hp0;
    ((__nv_bfloat162*)g_Ahi)[idx2 + 1] = hp1;
    ((__nv_bfloat162*)g_Alo)[idx2] = lp0;
    ((__nv_bfloat162*)g_Alo)[idx2 + 1] = lp1;
}

// ============ classifier: bf16 HMMA, BM=128 BN=64(40) K=128, 3-term ==========
#define CTILE_A (128 * SKEW * 2)
#define CTILE_Bc (64 * SKEW * 2)
#define CSTAGE (2 * CTILE_A + 2 * CTILE_Bc)
#define CSM_TOTAL (2 * CSTAGE)

__device__ __forceinline__ void clf_load_stage(uint32_t sbase, int m0, int kc, int M) {
    int tid = threadIdx.x;
    #pragma unroll
    for (int it = 0; it < 2; it++) {
        int id = it * 256 + tid;
        int row = id >> 2, seg = id & 3;
        uint32_t soff = (uint32_t)(row * SKEW + seg * 8) * 2;
        int gr = m0 + row;
        int ok = (gr < M) ? 16 : 0;
        size_t grc = (gr < M) ? (size_t)gr : 0;
        CP_ASYNC16(sbase + soff,           g_Ahi + grc * FH + kc + seg * 8, ok);
        CP_ASYNC16(sbase + CTILE_A + soff, g_Alo + grc * FH + kc + seg * 8, ok);
    }
    {
        int row = tid >> 2, seg = tid & 3;
        uint32_t soff = (uint32_t)(row * SKEW + seg * 8) * 2;
        CP_ASYNC16(sbase + 2 * CTILE_A + soff,            g_Wcthi + (size_t)row * FH + kc + seg * 8, 16);
        CP_ASYNC16(sbase + 2 * CTILE_A + CTILE_Bc + soff, g_Wctlo + (size_t)row * FH + kc + seg * 8, 16);
    }
}

__global__ void __launch_bounds__(256, 2) mma_clf(const float* __restrict__ bias,
                                                  float* __restrict__ out, int M) {
    extern __shared__ char smem[];
    uint32_t sb = smem_u32(smem);
    int tid = threadIdx.x, wid = tid >> 5, lane = tid & 31;
    int m0 = blockIdx.x * 128;
    int warp_m = wid & 3, warp_n = wid >> 2;

    float acc[2][4][4] = {};
    const int nch = FH >> 5;

    clf_load_stage(sb, m0, 0, M);
    CP_COMMIT;
    for (int c = 0; c < nch; c++) {
        if (c + 1 < nch) {
            clf_load_stage(sb + ((c + 1) & 1) * CSTAGE, m0, (c + 1) << 5, M);
            CP_COMMIT;
            CP_WAIT(1);
        } else {
            CP_WAIT(0);
        }
        __syncthreads();

        uint32_t stg = sb + (c & 1) * CSTAGE;
        uint32_t aAhi = stg, aAlo = stg + CTILE_A;
        uint32_t aBhi = stg + 2 * CTILE_A, aBlo = aBhi + CTILE_Bc;

        #pragma unroll
        for (int kk = 0; kk < 32; kk += 16) {
            uint32_t ah[2][4], al[2][4];
            #pragma unroll
            for (int mi = 0; mi < 2; mi++) {
                int row = warp_m * 32 + mi * 16 + (lane & 15);
                int col = kk + (lane >> 4) * 8;
                uint32_t off = (uint32_t)(row * SKEW + col) * 2;
                LDSM_X4(ah[mi][0], ah[mi][1], ah[mi][2], ah[mi][3], aAhi + off);
                LDSM_X4(al[mi][0], al[mi][1], al[mi][2], al[mi][3], aAlo + off);
            }
            uint32_t b[4][2];
            int g = lane >> 3;
            #pragma unroll
            for (int p = 0; p < 2; p++) {
                int nrow = warp_n * 32 + p * 16 + (g >> 1) * 8 + (lane & 7);
                int col = kk + (g & 1) * 8;
                uint32_t off = (uint32_t)(nrow * SKEW + col) * 2;
                uint32_t r0, r1, r2, r3;
                LDSM_X4(r0, r1, r2, r3, aBhi + off);
                b[p * 2][0] = r0; b[p * 2][1] = r1;
                b[p * 2 + 1][0] = r2; b[p * 2 + 1][1] = r3;
            }
            #pragma unroll
            for (int mi = 0; mi < 2; mi++)
                #pragma unroll
                for (int ni = 0; ni < 4; ni++) {
                    MMA16816(acc[mi][ni], ah[mi], b[ni]);
                    MMA16816(acc[mi][ni], al[mi], b[ni]);
                }
            #pragma unroll
            for (int p = 0; p < 2; p++) {
                int nrow = warp_n * 32 + p * 16 + (g >> 1) * 8 + (lane & 7);
                int col = kk + (g & 1) * 8;
                uint32_t off = (uint32_t)(nrow * SKEW + col) * 2;
                uint32_t r0, r1, r2, r3;
                LDSM_X4(r0, r1, r2, r3, aBlo + off);
                b[p * 2][0] = r0; b[p * 2][1] = r1;
                b[p * 2 + 1][0] = r2; b[p * 2 + 1][1] = r3;
            }
            #pragma unroll
            for (int mi = 0; mi < 2; mi++)
                #pragma unroll
                for (int ni = 0; ni < 4; ni++)
                    MMA16816(acc[mi][ni], ah[mi], b[ni]);
        }
        __syncthreads();
    }

    int gid = lane >> 2, tig = lane & 3;
    #pragma unroll
    for (int mi = 0; mi < 2; mi++) {
        #pragma unroll
        for (int ni = 0; ni < 4; ni++) {
            int col = warp_n * 32 + ni * 8 + tig * 2;
            if (col >= FC) continue;
            float b0 = bias[col], b1 = bias[col + 1];
            int r0 = m0 + warp_m * 32 + mi * 16 + gid;
            if (r0 < M)
                *(float2*)(out + (size_t)r0 * FC + col) =
                    make_float2(acc[mi][ni][0] + b0, acc[mi][ni][1] + b1);
            int r1 = r0 + 8;
            if (r1 < M)
                *(float2*)(out + (size_t)r1 * FC + col) =
                    make_float2(acc[mi][ni][2] + b0, acc[mi][ni][3] + b1);
        }
    }
}

// ---------------- launch ----------------
extern "C" void kernel_launch(void* const* d_in, const int* in_sizes, int n_in,
                              void* d_out, int out_size) {
    const float* x  = (const float*)d_in[0];
    const void*  ei = d_in[1];
    const float* W1 = (const float*)d_in[2];
    const float* b1 = (const float*)d_in[3];
    const float* W2 = (const float*)d_in[4];
    const float* b2 = (const float*)d_in[5];
    const float* Wc = (const float*)d_in[6];
    const float* bc = (const float*)d_in[7];
    float*       out = (float*)d_out;

    const int n = in_sizes[0] / F0;   // 100000
    const int E = in_sizes[1] / 2;    // 1600000

    cudaFuncSetAttribute(k2_gemm1_scatter, cudaFuncAttributeMaxDynamicSharedMemorySize, GSM_TOTAL);
    cudaFuncSetAttribute(mma_gemm2, cudaFuncAttributeMaxDynamicSharedMemorySize, GSM_TOTAL);
    cudaFuncSetAttribute(mma_clf, cudaFuncAttributeMaxDynamicSharedMemorySize, CSM_TOTAL);

    int zB    = (n + 255) / 256;
    int bDeg  = (E + 1023) / 1024;
    int bW1   = (F0 * FH + 255) / 256;
    int bW2   = (FH * FH + 255) / 256;
    int bWc   = (64 * FH + 255) / 256;
    int gemmB = (n + 127) / 128;
    int scatB = (E + 2047) / 2048;
    int dinvB = (n + 255) / 256;

    k0_detect_zero<<<1 + zB, 256>>>((const int*)ei, 2 * E, n);
    k1_prep<<<bDeg + bW1 + bW2 + bWc, 256>>>(ei, E, W1, W2, Wc, bDeg, bW1, bW2);
    k1b_scan_dinv<<<1 + dinvB, 256>>>(n);
    k2_gemm1_scatter<<<gemmB + scatB, 256, GSM_TOTAL>>>(x, ei, n, E, gemmB);
    agg_kernel<<<(n + 7) / 8, 256>>>(b1, n);
    mma_gemm2<<<gemmB, 256, GSM_TOTAL>>>(n);
    agg_kernel<<<(n + 7) / 8, 256>>>(b2, n);
    mma_clf<<<gemmB, 256, CSM_TOTAL>>>(bc, out, n);
}